// round 15
// baseline (speedup 1.0000x reference)
#include <cuda_runtime.h>
#include <math.h>

#define B4 4
#define NPT 4096
#define CH 64
#define KNN 16
#define NPTS (B4*NPT)          // 16384
#define NBST 20                // padded row stride for [64][16] smem tiles

typedef unsigned long long u64;

// ---------------- f32x2 packed math (FFMA2 — only reachable via PTX) ----------------
#define FMA2(acc, A_, B_) asm("fma.rn.f32x2 %0, %1, %2, %0;" : "+l"(acc) : "l"(A_), "l"(B_))
#define MUL2(out, A_, B_) asm("mul.rn.f32x2 %0, %1, %2;" : "=l"(out) : "l"(A_), "l"(B_))
#define ADD2(out, A_, B_) asm("add.rn.f32x2 %0, %1, %2;" : "=l"(out) : "l"(A_), "l"(B_))
#define PACK2(out, lo, hi) asm("mov.b64 %0, {%1, %2};" : "=l"(out) : "f"(lo), "f"(hi))
#define UNPK2(lo, hi, in) asm("mov.b64 {%0, %1}, %2;" : "=f"(lo), "=f"(hi) : "l"(in))

// per-group named barrier: 64 threads, barrier id = group+1
#define GBAR(gid) asm volatile("bar.sync %0, 64;" :: "r"((gid)+1) : "memory")

// packed 16-wide accumulate: Ac = u64[8] accumulators, Ww = packed (w,w), Bp = 16B-aligned 16-float row
#define ACC16P(Ac, Ww, Bp) do {                                          \
    const ulonglong2* p_ = (const ulonglong2*)(Bp);                      \
    ulonglong2 d0_ = p_[0], d1_ = p_[1], d2_ = p_[2], d3_ = p_[3];       \
    FMA2(Ac[0], Ww, d0_.x); FMA2(Ac[1], Ww, d0_.y);                      \
    FMA2(Ac[2], Ww, d1_.x); FMA2(Ac[3], Ww, d1_.y);                      \
    FMA2(Ac[4], Ww, d2_.x); FMA2(Ac[5], Ww, d2_.y);                      \
    FMA2(Ac[6], Ww, d3_.x); FMA2(Ac[7], Ww, d3_.y);                      \
} while (0)

// ---------------- scratch (device globals; no allocation) ----------------
__device__ float g_f1T[B4*NPT*CH];
__device__ float g_f2T[B4*NPT*CH];
__device__ float g_x1T[B4*NPT*3];
__device__ float g_x2T[B4*NPT*3];
__device__ float g_p2nT[B4*NPT*CH];
__device__ int   g_idx1[B4*NPT*KNN];
__device__ int   g_idx2[B4*NPT*KNN];
// column-major weights [c][o]: lane o reads [c*64+o] -> coalesced 128B/warp, L1-resident
__device__ float g_wv1T[132*64];    // rows 0..130 used (131 padded to 132)
__device__ float g_wk1T[64*64];
__device__ float g_wm1T[64*16];     // stored NEGATED (used only as h -= w*k)
__device__ float g_WmqT[64*16];
__device__ float g_wp1T[5*64];
__device__ float g_wq2T[64*64];
__device__ float g_wk2T[64*64];
__device__ float g_wv2T[64*64];
__device__ float g_wp2T[4*64];

// ---------------- weight prep ----------------
__global__ void prep_weights(const float* __restrict__ wq1, const float* __restrict__ wk1,
                             const float* __restrict__ wv1, const float* __restrict__ wm1,
                             const float* __restrict__ wp1, const float* __restrict__ wq2,
                             const float* __restrict__ wk2, const float* __restrict__ wv2,
                             const float* __restrict__ wp2)
{
    int t = threadIdx.x;
    for (int i = t; i < 132*64; i += 256) {
        int c = i / 64, o = i % 64;
        g_wv1T[i] = (c < 131) ? wv1[o*131 + c] : 0.f;
    }
    for (int i = t; i < 64*64; i += 256) {
        int c = i / 64, o = i % 64;
        g_wk1T[i] = wk1[o*64+c];
        g_wq2T[i] = wq2[o*64+c];
        g_wk2T[i] = wk2[o*64+c];
        g_wv2T[i] = wv2[o*64+c];
    }
    for (int i = t; i < 16*64; i += 256) { int j = i/64, o = i%64; g_wm1T[o*16+j] = -wm1[i]; }
    for (int i = t; i < 64*5;  i += 256) { int o = i/5,  r = i%5;  g_wp1T[r*64+o] = wp1[i]; }
    for (int i = t; i < 64*4;  i += 256) { int o = i/4,  r = i%4;  g_wp2T[r*64+o] = wp2[i]; }
    // WmqT[c*16+j] = sum_o wm1[j][o] * wq1[o][c]
    for (int i = t; i < 64*16; i += 256) {
        int c = i/16, j = i%16;
        float s = 0.f;
        for (int o = 0; o < 64; o++) s += wm1[j*64+o] * wq1[o*64+c];
        g_WmqT[c*16+j] = s;
    }
}

// ---------------- transposes (merged: z selects tensor) ----------------
__global__ void transpose_feat(const float* __restrict__ in1, const float* __restrict__ in2)
{
    __shared__ float tile[64][65];
    int which = blockIdx.z;
    const float* in = which ? in2 : in1;
    float* out = which ? g_f2T : g_f1T;
    int b = blockIdx.y, n0 = blockIdx.x * 64;
    int tx = threadIdx.x, ty = threadIdx.y;
    for (int c = ty; c < 64; c += 8)
        tile[c][tx] = in[(b*64 + c)*NPT + n0 + tx];
    __syncthreads();
    for (int nn = ty; nn < 64; nn += 8)
        out[(b*NPT + n0 + nn)*64 + tx] = tile[tx][nn];
}

__global__ void transpose_xyz(const float* __restrict__ in1, const float* __restrict__ in2)
{
    int which = blockIdx.z;
    const float* in = which ? in2 : in1;
    float* out = which ? g_x2T : g_x1T;
    int i = blockIdx.x * blockDim.x + threadIdx.x;
    if (i < B4*NPT) {
        int b = i >> 12, n = i & (NPT-1);
        out[i*3+0] = in[b*3*NPT + n];
        out[i*3+1] = in[b*3*NPT + NPT + n];
        out[i*3+2] = in[b*3*NPT + 2*NPT + n];
    }
}

// sorted-descending insert of d into bd[16] (bd[0]=worst), guarded by d<bd[0]
#define INSERT16(d_) do {                                                 \
    float dv_ = (d_);                                                     \
    if (dv_ < bd[0]) {                                                    \
        _Pragma("unroll")                                                 \
        for (int t_ = 0; t_ < 15; t_++)                                   \
            bd[t_] = (dv_ < bd[t_+1]) ? bd[t_+1] : ((dv_ < bd[t_]) ? dv_ : bd[t_]); \
        bd[15] = (dv_ < bd[15]) ? dv_ : bd[15];                           \
    }                                                                     \
} while (0)

// ---------------- brute-force KNN (3-phase, packed-pair scan): 4 threads/query ----------------
#define NPAIR 2048
#define KQ 128                   // queries per block
#define KTH 512                  // threads per block
#define KNN_SMEM (65536 + 32768 + 1024 + 512)
__global__ __launch_bounds__(KTH) void knn_both(const float* __restrict__ xyz1,
                                                const float* __restrict__ xyz2)
{
    extern __shared__ char smem_raw[];
    u64* sX = (u64*)smem_raw;                 // 2048 pairs
    u64* sY = sX + NPAIR;
    u64* sZ = sY + NPAIR;
    u64* sS = sZ + NPAIR;
    char* tail = (char*)(sS + NPAIR);
    float* svals = (float*)tail;                      // [128][64]  (phase 1.5 only)
    int*   sless = (int*)tail;                        // [128][16]  (phase 2; overlays svals)
    int*   seq   = (int*)(tail + 8192);               // [128][32]  (phase 2; overlays svals)
    int*   scnt  = (int*)(tail + 32768);              // [128][2]
    float* sthr  = (float*)(tail + 32768 + 1024);     // [128]

    int which = blockIdx.z;          // 0: cand=xyz2 -> g_idx1, 1: cand=xyz1 -> g_idx2
    const float* cxyz = which ? xyz1 : xyz2;
    int* out = which ? g_idx2 : g_idx1;
    int b = blockIdx.y;
    const float* cb = cxyz + b*3*NPT;
    int tid = threadIdx.x;
    for (int idx = tid; idx < NPAIR; idx += KTH) {
        int i0 = idx*2, i1 = i0+1;
        float x0 = cb[i0],        x1 = cb[i1];
        float y0 = cb[NPT+i0],    y1 = cb[NPT+i1];
        float z0 = cb[2*NPT+i0],  z1 = cb[2*NPT+i1];
        float s0 = __fadd_rn(__fadd_rn(__fmul_rn(x0,x0), __fmul_rn(y0,y0)), __fmul_rn(z0,z0));
        float s1 = __fadd_rn(__fadd_rn(__fmul_rn(x1,x1), __fmul_rn(y1,y1)), __fmul_rn(z1,z1));
        u64 t;
        PACK2(t, x0, x1); sX[idx] = t;
        PACK2(t, y0, y1); sY[idx] = t;
        PACK2(t, z0, z1); sZ[idx] = t;
        PACK2(t, s0, s1); sS[idx] = t;
    }
    if (tid < 2*KQ) scnt[tid] = 0;
    __syncthreads();

    int ql = tid >> 2, part = tid & 3;
    int n = blockIdx.x * KQ + ql;
    const float* qb = xyz1 + b*3*NPT;
    float qx = qb[n], qy = qb[NPT+n], qz = qb[2*NPT+n];
    float q2 = __fadd_rn(__fadd_rn(__fmul_rn(qx,qx), __fmul_rn(qy,qy)), __fmul_rn(qz,qz));
    u64 qxp, qyp, qzp, q2p, m2p;
    PACK2(qxp, qx, qx); PACK2(qyp, qy, qy); PACK2(qzp, qz, qz);
    PACK2(q2p, q2, q2); PACK2(m2p, -2.0f, -2.0f);

    // Phase 1: sorted-descending value list + 4-deep shift queue
    float bd[16];
#pragma unroll
    for (int t = 0; t < 16; t++) bd[t] = 3.0e38f;
    float gate = 3.0e38f;
    float tq0 = 0.f, tq1 = 0.f, tq2 = 0.f, tq3 = 0.f;
    int cnt = 0;

#pragma unroll 2
    for (int j = 0; j < 512; j++) {
        int pi = (j << 2) | part;                  // pair index; candidates 2pi, 2pi+1
        u64 X = sX[pi], Y = sY[pi], Z = sZ[pi], S = sS[pi];
        u64 cr; MUL2(cr, qxp, X); FMA2(cr, qyp, Y); FMA2(cr, qzp, Z);
        u64 dd; ADD2(dd, q2p, S); FMA2(dd, m2p, cr);
        float d0, d1; UNPK2(d0, d1, dd);
        if (d0 <= gate) { tq3 = tq2; tq2 = tq1; tq1 = tq0; tq0 = d0; cnt++; }
        if (d1 <= gate) { tq3 = tq2; tq2 = tq1; tq1 = tq0; tq0 = d1; cnt++; }
        if (__ballot_sync(0xffffffffu, cnt >= 3)) {
            if (cnt >= 1) INSERT16(tq0);
            if (cnt >= 2) INSERT16(tq1);
            if (cnt >= 3) INSERT16(tq2);
            if (cnt >= 4) INSERT16(tq3);
            cnt = 0;
            float w = bd[0];
            w = fminf(w, __shfl_xor_sync(0xffffffffu, w, 1));
            w = fminf(w, __shfl_xor_sync(0xffffffffu, w, 2));
            gate = w;
        }
    }
    if (cnt >= 1) INSERT16(tq0);
    if (cnt >= 2) INSERT16(tq1);
    if (cnt >= 3) INSERT16(tq2);
    if (cnt >= 4) INSERT16(tq3);

#pragma unroll
    for (int r = 0; r < 16; r++) svals[ql*64 + part*16 + r] = bd[15-r];
    __syncthreads();

    // Phase 1.5: 4-list merge -> thr (one thread per query)
    if (part == 0) {
        const float* L = svals + ql*64;
        int p0 = 0, p1 = 0, p2 = 0, p3 = 0;
        float last = 0.f;
        for (int r = 0; r < 16; r++) {
            float v0 = L[p0], v1 = L[16+p1], v2 = L[32+p2], v3 = L[48+p3];
            float m;
            if (v0 <= v1 && v0 <= v2 && v0 <= v3) { m = v0; p0++; }
            else if (v1 <= v2 && v1 <= v3)        { m = v1; p1++; }
            else if (v2 <= v3)                    { m = v2; p2++; }
            else                                  { m = v3; p3++; }
            last = m;
        }
        sthr[ql] = last;
    }
    __syncthreads();     // after this, svals is dead -> sless/seq may overlay it

    // Phase 2: rescan with identical packed arithmetic; collect indices
    float thr = sthr[ql];
#pragma unroll 2
    for (int j = 0; j < 512; j++) {
        int pi = (j << 2) | part;
        u64 X = sX[pi], Y = sY[pi], Z = sZ[pi], S = sS[pi];
        u64 cr; MUL2(cr, qxp, X); FMA2(cr, qyp, Y); FMA2(cr, qzp, Z);
        u64 dd; ADD2(dd, q2p, S); FMA2(dd, m2p, cr);
        float d0, d1; UNPK2(d0, d1, dd);
        if (d0 <= thr) {
            int i = pi*2;
            if (d0 < thr) {
                int pos = atomicAdd(&scnt[ql*2 + 0], 1);
                sless[ql*16 + pos] = i;            // provably pos <= 14
            } else {
                int pos = atomicAdd(&scnt[ql*2 + 1], 1);
                if (pos < 32) seq[ql*32 + pos] = i;
            }
        }
        if (d1 <= thr) {
            int i = pi*2 + 1;
            if (d1 < thr) {
                int pos = atomicAdd(&scnt[ql*2 + 0], 1);
                sless[ql*16 + pos] = i;
            } else {
                int pos = atomicAdd(&scnt[ql*2 + 1], 1);
                if (pos < 32) seq[ql*32 + pos] = i;
            }
        }
    }
    __syncthreads();

    // Finalize: sort the <thr indices, append `need` smallest ==thr indices
    if (part == 0) {
        int nl = scnt[ql*2 + 0];
        int ne = scnt[ql*2 + 1]; if (ne > 32) ne = 32;
        int need = 16 - nl;
        int* Ls = sless + ql*16;
        for (int a = 1; a < nl; a++) {
            int v = Ls[a]; int bp = a;
            while (bp > 0 && Ls[bp-1] > v) { Ls[bp] = Ls[bp-1]; bp--; }
            Ls[bp] = v;
        }
        int* Es = seq + ql*32;
        int base = (b*NPT + n)*16;
        for (int r = 0; r < nl; r++) out[base + r] = Ls[r];
        for (int r = 0; r < need; r++) {
            int mi = 0x7fffffff, mp = 0;
            for (int a = 0; a < ne; a++) if (Es[a] < mi) { mi = Es[a]; mp = a; }
            Es[mp] = 0x7fffffff;
            out[base + nl + r] = mi;
        }
    }
}

// ---------------- group1 (weights via coalesced L1 LDG; smem 54KB -> 3 blocks/SM) ----------------
#define GSZ1 2784
#define G1_SMEM ((2448 + 4*GSZ1)*4)
__global__ __launch_bounds__(256, 3) void group1_kernel(const float* __restrict__ wm2,
                                                        const float* __restrict__ bpos1,
                                                        int groups_total, int iters)
{
    extern __shared__ float sm[];
    float* s_wm1T = sm;                 // 1024  [op][16] (negated)
    float* s_WmqT = s_wm1T + 1024;      // 1024  [c][16]
    float* s_wp1T = s_WmqT + 1024;      // 320   [r][64]
    float* s_wm2  = s_wp1T + 320;       // 16
    float* s_b1   = s_wm2  + 16;        // 64
    float* s_grp0 = s_b1   + 64;

    int tid = threadIdx.x;
    for (int i = tid; i < 1024; i += 256) { s_wm1T[i] = g_wm1T[i]; s_WmqT[i] = g_WmqT[i]; }
    for (int i = tid; i < 320;  i += 256) s_wp1T[i] = g_wp1T[i];
    if (tid < 16) s_wm2[tid] = wm2[tid];
    if (tid < 64) s_b1[tid] = bpos1[tid];

    int g = tid >> 6, o = tid & 63;
    float* snb  = s_grp0 + g*GSZ1;      // [64][20], later reused for k
    float* svpe = snb  + 64*NBST;       // [64][20]
    float* spts = svpe + 64*NBST;       // 64
    float* spos = spts + 64;            // [5][16]
    float* smq  = spos + 80;            // 16
    float* slog = smq  + 16;            // 16
    float* sfn2 = slog + 16;            // 16 (cross-warp partials)
    float* smqp = sfn2 + 16;            // 16
    int*   sidx = (int*)(smqp + 16);    // 16
    int gg = blockIdx.x * 4 + g;
    int sU = o & 15, qt = o >> 4;       // distributed fn2/mq assignment
    __syncthreads();                    // weights visible to all groups

    for (int it = 0; it < iters; it++) {
        int p = gg + it * groups_total;
        bool active = p < NPTS;
        int b = p >> 12;

        if (active) {
            if (o < 16) sidx[o] = g_idx1[(p<<4) + o];
            spts[o] = g_f1T[(p<<6) + o];
        }
        GBAR(g);
        if (active) {
#pragma unroll
            for (int s = 0; s < 16; s++) {
                int id = sidx[s];
                snb[o*NBST + s] = g_f2T[(((b<<12) + id)<<6) + o];
            }
        }
        GBAR(g);

        // vbase = wv1[o][0:64] . pts  (coalesced weight LDG per c)
        float vbase = 0.f;
#pragma unroll 8
        for (int c = 0; c < 64; c++)
            vbase = __fmaf_rn(__ldg(&g_wv1T[c*64 + o]), spts[c], vbase);

        // distributed fn2 / mq: 4 threads per neighbor s, 16 channels each
        {
            float fn2p = 0.f, mqp = 0.f;
#pragma unroll
            for (int cc = 0; cc < 16; cc++) {
                int c = qt*16 + cc;
                float pv = spts[c];
                float t = pv - snb[c*NBST + sU];
                fn2p = __fmaf_rn(t, t, fn2p);
                mqp  = __fmaf_rn(s_WmqT[c*16 + sU], pv, mqp);
            }
            fn2p += __shfl_xor_sync(0xffffffffu, fn2p, 16);
            mqp  += __shfl_xor_sync(0xffffffffu, mqp, 16);
            if (o >= 32 && o < 48) { sfn2[sU] = fn2p; smqp[sU] = mqp; }
            GBAR(g);
            if (active && o < 16) {
                int s = o; int id = sidx[s];
                const float* q3 = g_x1T + p*3;
                const float* c3 = g_x2T + ((b<<12) + id)*3;
                float dx = q3[0]-c3[0], dy = q3[1]-c3[1], dz = q3[2]-c3[2];
                spos[0*16+s] = sqrtf(fn2p + sfn2[s]);
                spos[1*16+s] = sqrtf(dx*dx + dy*dy + dz*dz);
                spos[2*16+s] = dx; spos[3*16+s] = dy; spos[4*16+s] = dz;
                smq[s] = mqp + smqp[s];
            }
        }
        GBAR(g);

        // v[s] packed: va[k] = (v[2k], v[2k+1])
        u64 va[8];
        {
            u64 vb2; PACK2(vb2, vbase, vbase);
#pragma unroll
            for (int k = 0; k < 8; k++) va[k] = vb2;
        }
#pragma unroll
        for (int jj = 0; jj < 3; jj++) {
            float wj = __ldg(&g_wv1T[(128+jj)*64 + o]);
            u64 ww; PACK2(ww, wj, wj);
            ACC16P(va, ww, spos + (2+jj)*16);
        }
#pragma unroll 4
        for (int c = 0; c < 64; c++) {
            float wc = __ldg(&g_wv1T[(64+c)*64 + o]);
            u64 ww; PACK2(ww, wc, wc);
            ACC16P(va, ww, snb + c*NBST);
        }
        // pos_enc packed
        u64 pea[8];
        {
            float bb = s_b1[o];
            u64 bb2; PACK2(bb2, bb, bb);
#pragma unroll
            for (int k = 0; k < 8; k++) pea[k] = bb2;
        }
#pragma unroll
        for (int r = 0; r < 5; r++) {
            float wr = s_wp1T[r*64 + o];
            u64 ww; PACK2(ww, wr, wr);
            ACC16P(pea, ww, spos + r*16);
        }
        // svpe = v + pe
        {
            ulonglong2* dst = (ulonglong2*)(svpe + o*NBST);
#pragma unroll
            for (int k = 0; k < 4; k++) {
                u64 lo, hi;
                ADD2(lo, va[2*k],   pea[2*k]);
                ADD2(hi, va[2*k+1], pea[2*k+1]);
                ulonglong2 w2v; w2v.x = lo; w2v.y = hi;
                dst[k] = w2v;
            }
        }
        GBAR(g);

        // k[s] packed
        u64 ka[8];
#pragma unroll
        for (int k = 0; k < 8; k++) ka[k] = 0ull;
#pragma unroll 4
        for (int c = 0; c < 64; c++) {
            float wc = __ldg(&g_wk1T[c*64 + o]);
            u64 ww; PACK2(ww, wc, wc);
            ACC16P(ka, ww, svpe + c*NBST);
        }
        {
            ulonglong2* dst = (ulonglong2*)(snb + o*NBST);   // snb reused as k buffer
#pragma unroll
            for (int k = 0; k < 4; k++) {
                ulonglong2 w2v; w2v.x = ka[2*k]; w2v.y = ka[2*k+1];
                dst[k] = w2v;
            }
        }
        GBAR(g);

        // attn logits: h = relu(mq - wm1 @ k)  (wm1 pre-negated -> pure FMA2 accumulate)
        {
            int j = o & 15, sb = o >> 4;
            float mqj = smq[j];
            u64 hp0, hp1;
            PACK2(hp0, mqj, mqj); PACK2(hp1, mqj, mqj);
#pragma unroll 8
            for (int op = 0; op < 64; op++) {
                float w = s_wm1T[op*16 + j];     // = -wm1
                u64 ww; PACK2(ww, w, w);
                const ulonglong2* nbp = (const ulonglong2*)(snb + op*NBST + sb*4);
                ulonglong2 nbv = nbp[0];
                FMA2(hp0, ww, nbv.x);
                FMA2(hp1, ww, nbv.y);
            }
            float h0, h1, h2, h3;
            UNPK2(h0, h1, hp0); UNPK2(h2, h3, hp1);
            float wj = s_wm2[j];
            float hq[4] = {h0, h1, h2, h3};
#pragma unroll
            for (int ss = 0; ss < 4; ss++) {
                float part = wj * fmaxf(hq[ss], 0.f);
                part += __shfl_xor_sync(0xffffffffu, part, 1);
                part += __shfl_xor_sync(0xffffffffu, part, 2);
                part += __shfl_xor_sync(0xffffffffu, part, 4);
                part += __shfl_xor_sync(0xffffffffu, part, 8);
                if (j == 0) slog[sb*4 + ss] = part;
            }
        }
        GBAR(g);

        // softmax + weighted sum + leaky
        float v[16];
#pragma unroll
        for (int k = 0; k < 8; k++) UNPK2(v[2*k], v[2*k+1], va[k]);
        float mx = -3.0e38f;
#pragma unroll
        for (int s = 0; s < 16; s++) mx = fmaxf(mx, slog[s]);
        float sum = 0.f, outv = 0.f;
#pragma unroll
        for (int s = 0; s < 16; s++) {
            float e = __expf(slog[s] - mx);
            sum += e; outv += e * v[s];
        }
        outv /= sum;
        outv = (outv >= 0.f) ? outv : 0.1f*outv;
        if (active) g_p2nT[(p<<6) + o] = outv;
        GBAR(g);
    }
}

// ---------------- group2 (weights via coalesced L1 LDG; smem 45KB -> 3+ blocks/SM) ----------------
#define GSZ2 2752
#define G2_SMEM ((320 + 4*GSZ2)*4)
__global__ __launch_bounds__(256, 3) void group2_kernel(const float* __restrict__ bpos2,
                                                        float* __restrict__ outp,
                                                        int groups_total, int iters)
{
    extern __shared__ float sm[];
    float* s_wp2T = sm;                 // 256
    float* s_b2   = s_wp2T + 256;       // 64
    float* s_grp0 = s_b2   + 64;

    int tid = threadIdx.x;
    for (int i = tid; i < 256; i += 256) s_wp2T[i] = g_wp2T[i];
    if (tid < 64) s_b2[tid] = bpos2[tid];

    int g = tid >> 6, o = tid & 63;
    float* snb  = s_grp0 + g*GSZ2;      // [64][20]
    float* stmp = snb  + 64*NBST;       // [64][20]
    float* spts = stmp + 64*NBST;       // 64
    float* spos = spts + 64;            // [4][16]
    float* slog = spos + 64;            // 16 (scratch)
    float* sred = slog + 16;            // 32
    int*   sidx = (int*)(sred + 32);    // 16
    int gg = blockIdx.x * 4 + g;
    __syncthreads();                    // weights visible to all groups

    for (int it = 0; it < iters; it++) {
        int p = gg + it * groups_total;
        bool active = p < NPTS;
        int b = p >> 12, n = p & (NPT-1);

        if (active) {
            if (o < 16) sidx[o] = g_idx2[(p<<4) + o];
            spts[o] = g_p2nT[(p<<6) + o];
        }
        GBAR(g);
        if (active) {
#pragma unroll
            for (int s = 0; s < 16; s++) {
                int id = sidx[s];
                snb[o*NBST + s] = g_p2nT[(((b<<12) + id)<<6) + o];
            }
        }
        GBAR(g);

        float q = 0.f;
#pragma unroll 8
        for (int c = 0; c < 64; c++)
            q = __fmaf_rn(__ldg(&g_wq2T[c*64 + o]), spts[c], q);
        q *= 0.125f;   // 64^-0.5

        if (active && o < 16) {
            int s = o; int id = sidx[s];
            const float* q3 = g_x1T + p*3;
            const float* c3 = g_x1T + ((b<<12) + id)*3;
            float dx = q3[0]-c3[0], dy = q3[1]-c3[1], dz = q3[2]-c3[2];
            spos[0*16+s] = dx; spos[1*16+s] = dy; spos[2*16+s] = dz;
            spos[3*16+s] = sqrtf(dx*dx + dy*dy + dz*dz);
        }
        GBAR(g);

        // pos_enc packed
        u64 pea[8];
        {
            float bb = s_b2[o];
            u64 bb2; PACK2(bb2, bb, bb);
#pragma unroll
            for (int k = 0; k < 8; k++) pea[k] = bb2;
        }
#pragma unroll
        for (int r = 0; r < 4; r++) {
            float wr = s_wp2T[r*64 + o];
            u64 ww; PACK2(ww, wr, wr);
            ACC16P(pea, ww, spos + r*16);
        }
        // stmp = nb + pe
        {
            const ulonglong2* src = (const ulonglong2*)(snb + o*NBST);
            ulonglong2* dst = (ulonglong2*)(stmp + o*NBST);
#pragma unroll
            for (int k = 0; k < 4; k++) {
                ulonglong2 nbv = src[k];
                u64 lo, hi;
                ADD2(lo, nbv.x, pea[2*k]);
                ADD2(hi, nbv.y, pea[2*k+1]);
                ulonglong2 w2v; w2v.x = lo; w2v.y = hi;
                dst[k] = w2v;
            }
        }
        GBAR(g);

        // k = wk2 @ tmp ; v = wv2 @ nb  (packed, coalesced weight LDG per c)
        u64 ka[8], vva[8];
#pragma unroll
        for (int k = 0; k < 8; k++) { ka[k] = 0ull; vva[k] = 0ull; }
#pragma unroll 2
        for (int c = 0; c < 64; c++) {
            float wk = __ldg(&g_wk2T[c*64 + o]);
            float wv = __ldg(&g_wv2T[c*64 + o]);
            u64 wwk, wwv;
            PACK2(wwk, wk, wk); PACK2(wwv, wv, wv);
            ACC16P(ka,  wwk, stmp + c*NBST);
            ACC16P(vva, wwv, snb  + c*NBST);
        }
        float kk[16], vv[16];
#pragma unroll
        for (int k = 0; k < 8; k++) {
            UNPK2(kk[2*k], kk[2*k+1], ka[k]);
            UNPK2(vv[2*k], vv[2*k+1], vva[k]);
        }

        // logits[s] = sum_o q[o]*k[o][s] : warp reduce then cross-warp via smem
#pragma unroll
        for (int s = 0; s < 16; s++) {
            float x = q * kk[s];
            x += __shfl_xor_sync(0xffffffffu, x, 16);
            x += __shfl_xor_sync(0xffffffffu, x, 8);
            x += __shfl_xor_sync(0xffffffffu, x, 4);
            x += __shfl_xor_sync(0xffffffffu, x, 2);
            x += __shfl_xor_sync(0xffffffffu, x, 1);
            kk[s] = x;
        }
        if ((o & 31) == 0) {
#pragma unroll
            for (int s = 0; s < 16; s++) sred[(o>>5)*16 + s] = kk[s];
        }
        GBAR(g);

        float lg[16];
#pragma unroll
        for (int s = 0; s < 16; s++) lg[s] = sred[s] + sred[16+s];
        float mx = -3.0e38f;
#pragma unroll
        for (int s = 0; s < 16; s++) mx = fmaxf(mx, lg[s]);
        float sum = 0.f, outv = 0.f;
#pragma unroll
        for (int s = 0; s < 16; s++) {
            float e = __expf(lg[s] - mx);
            sum += e; outv += e * vv[s];
        }
        outv /= sum;
        outv = (outv >= 0.f) ? outv : 0.1f*outv;
        if (active) outp[(b*64 + o)*NPT + n] = outv;
        GBAR(g);
    }
}

// ---------------- launch ----------------
extern "C" void kernel_launch(void* const* d_in, const int* in_sizes, int n_in,
                              void* d_out, int out_size)
{
    const float* xyz1  = (const float*)d_in[0];
    const float* feat1 = (const float*)d_in[1];
    const float* xyz2  = (const float*)d_in[2];
    const float* feat2 = (const float*)d_in[3];
    const float* wq1   = (const float*)d_in[4];
    const float* wk1   = (const float*)d_in[5];
    const float* wv1   = (const float*)d_in[6];
    const float* wm1   = (const float*)d_in[7];
    const float* wm2   = (const float*)d_in[8];
    const float* wp1   = (const float*)d_in[9];
    const float* b1    = (const float*)d_in[10];
    const float* wq2   = (const float*)d_in[11];
    const float* wk2   = (const float*)d_in[12];
    const float* wv2   = (const float*)d_in[13];
    const float* wp2   = (const float*)d_in[14];
    const float* b2    = (const float*)d_in[15];
    float* out = (float*)d_out;

    cudaFuncSetAttribute(knn_both,      cudaFuncAttributeMaxDynamicSharedMemorySize, KNN_SMEM);
    cudaFuncSetAttribute(group1_kernel, cudaFuncAttributeMaxDynamicSharedMemorySize, G1_SMEM);
    cudaFuncSetAttribute(group2_kernel, cudaFuncAttributeMaxDynamicSharedMemorySize, G2_SMEM);

    const int GRID = 444;                 // 3 blocks/SM on 148 SMs
    const int GROUPS = GRID * 4;          // 1776 point-groups
    const int ITERS = (NPTS + GROUPS - 1) / GROUPS;   // 10

    prep_weights<<<1, 256>>>(wq1, wk1, wv1, wm1, wp1, wq2, wk2, wv2, wp2);   // 0
    transpose_feat<<<dim3(64, B4, 2), dim3(64, 8)>>>(feat1, feat2);          // 1
    transpose_xyz<<<dim3(64, 1, 2), 256>>>(xyz1, xyz2);                      // 2
    knn_both<<<dim3(NPT/KQ, B4, 2), KTH, KNN_SMEM>>>(xyz1, xyz2);            // 3
    group1_kernel<<<GRID, 256, G1_SMEM>>>(wm2, b1, GROUPS, ITERS);           // 4
    group2_kernel<<<GRID, 256, G2_SMEM>>>(b2, out, GROUPS, ITERS);           // 5
}

// round 16
// speedup vs baseline: 1.0572x; 1.0572x over previous
#include <cuda_runtime.h>
#include <math.h>

#define B4 4
#define NPT 4096
#define CH 64
#define KNN 16
#define NPTS (B4*NPT)          // 16384
#define NBST 20                // padded row stride for [64][16] smem tiles
#define WV1S 132               // row stride for wv1 [64][132] (131 used)
#define W64S 68                // row stride for 64x64 weights [64][68]

typedef unsigned long long u64;

// ---------------- f32x2 packed math (FFMA2 — only reachable via PTX) ----------------
#define FMA2(acc, A_, B_) asm("fma.rn.f32x2 %0, %1, %2, %0;" : "+l"(acc) : "l"(A_), "l"(B_))
#define MUL2(out, A_, B_) asm("mul.rn.f32x2 %0, %1, %2;" : "=l"(out) : "l"(A_), "l"(B_))
#define ADD2(out, A_, B_) asm("add.rn.f32x2 %0, %1, %2;" : "=l"(out) : "l"(A_), "l"(B_))
#define PACK2(out, lo, hi) asm("mov.b64 %0, {%1, %2};" : "=l"(out) : "f"(lo), "f"(hi))
#define UNPK2(lo, hi, in) asm("mov.b64 {%0, %1}, %2;" : "=f"(lo), "=f"(hi) : "l"(in))

// per-group named barrier: 64 threads, barrier id = group+1
#define GBAR(gid) asm volatile("bar.sync %0, 64;" :: "r"((gid)+1) : "memory")

// packed 16-wide accumulate: Ac = u64[8] accumulators, Ww = packed (w,w), Bp = 16B-aligned 16-float row
#define ACC16P(Ac, Ww, Bp) do {                                          \
    const ulonglong2* p_ = (const ulonglong2*)(Bp);                      \
    ulonglong2 d0_ = p_[0], d1_ = p_[1], d2_ = p_[2], d3_ = p_[3];       \
    FMA2(Ac[0], Ww, d0_.x); FMA2(Ac[1], Ww, d0_.y);                      \
    FMA2(Ac[2], Ww, d1_.x); FMA2(Ac[3], Ww, d1_.y);                      \
    FMA2(Ac[4], Ww, d2_.x); FMA2(Ac[5], Ww, d2_.y);                      \
    FMA2(Ac[6], Ww, d3_.x); FMA2(Ac[7], Ww, d3_.y);                      \
} while (0)

// ---------------- scratch (device globals; no allocation) ----------------
__device__ float g_f1T[B4*NPT*CH];
__device__ float g_f2T[B4*NPT*CH];
__device__ float g_x1T[B4*NPT*3];
__device__ float g_x2T[B4*NPT*3];
__device__ float g_p2nT[B4*NPT*CH];
__device__ int   g_idx1[B4*NPT*KNN];
__device__ int   g_idx2[B4*NPT*KNN];
__device__ float g_wv1R[64*WV1S];
__device__ float g_wk1R[64*W64S];
__device__ float g_wm1T[64*16];     // stored NEGATED (used only as h -= w*k)
__device__ float g_WmqT[64*16];
__device__ float g_wp1T[5*64];
__device__ float g_wq2R[64*W64S];
__device__ float g_wk2R[64*W64S];
__device__ float g_wv2R[64*W64S];
__device__ float g_wp2T[4*64];

// ---------------- transposes (merged: z selects tensor) ----------------
__global__ void transpose_feat(const float* __restrict__ in1, const float* __restrict__ in2)
{
    __shared__ float tile[64][65];
    int which = blockIdx.z;
    const float* in = which ? in2 : in1;
    float* out = which ? g_f2T : g_f1T;
    int b = blockIdx.y, n0 = blockIdx.x * 64;
    int tx = threadIdx.x, ty = threadIdx.y;
    for (int c = ty; c < 64; c += 8)
        tile[c][tx] = in[(b*64 + c)*NPT + n0 + tx];
    __syncthreads();
    for (int nn = ty; nn < 64; nn += 8)
        out[(b*NPT + n0 + nn)*64 + tx] = tile[tx][nn];
}

// transpose_xyz + (block x==0,z==0 only) weight prep — keeps launch count low so
// the profiler's fixed skip lands on group1_kernel.
__global__ void transpose_xyz_prep(const float* __restrict__ in1, const float* __restrict__ in2,
                                   const float* __restrict__ wq1, const float* __restrict__ wk1,
                                   const float* __restrict__ wv1, const float* __restrict__ wm1,
                                   const float* __restrict__ wp1, const float* __restrict__ wq2,
                                   const float* __restrict__ wk2, const float* __restrict__ wv2,
                                   const float* __restrict__ wp2)
{
    int which = blockIdx.z;
    const float* in = which ? in2 : in1;
    float* out = which ? g_x2T : g_x1T;
    int i = blockIdx.x * blockDim.x + threadIdx.x;
    if (i < B4*NPT) {
        int b = i >> 12, n = i & (NPT-1);
        out[i*3+0] = in[b*3*NPT + n];
        out[i*3+1] = in[b*3*NPT + NPT + n];
        out[i*3+2] = in[b*3*NPT + 2*NPT + n];
    }
    if (blockIdx.x == 0 && blockIdx.z == 0) {
        int t = threadIdx.x;
        for (int k = t; k < 64*WV1S; k += 256) {
            int o = k / WV1S, c = k % WV1S;
            g_wv1R[k] = (c < 131) ? wv1[o*131 + c] : 0.f;
        }
        for (int k = t; k < 64*W64S; k += 256) {
            int o = k / W64S, c = k % W64S;
            float a = 0.f, bb = 0.f, d = 0.f, e = 0.f;
            if (c < 64) { a = wk1[o*64+c]; bb = wq2[o*64+c]; d = wk2[o*64+c]; e = wv2[o*64+c]; }
            g_wk1R[k] = a; g_wq2R[k] = bb; g_wk2R[k] = d; g_wv2R[k] = e;
        }
        for (int k = t; k < 16*64; k += 256) { int j = k/64, o = k%64; g_wm1T[o*16+j] = -wm1[k]; }
        for (int k = t; k < 64*5;  k += 256) { int o = k/5,  r = k%5;  g_wp1T[r*64+o] = wp1[k]; }
        for (int k = t; k < 64*4;  k += 256) { int o = k/4,  r = k%4;  g_wp2T[r*64+o] = wp2[k]; }
        for (int k = t; k < 64*16; k += 256) {
            int c = k/16, j = k%16;
            float s = 0.f;
            for (int o = 0; o < 64; o++) s += wm1[j*64+o] * wq1[o*64+c];
            g_WmqT[c*16+j] = s;
        }
    }
}

// sorted-descending insert of d into bd[16] (bd[0]=worst), guarded by d<bd[0]
#define INSERT16(d_) do {                                                 \
    float dv_ = (d_);                                                     \
    if (dv_ < bd[0]) {                                                    \
        _Pragma("unroll")                                                 \
        for (int t_ = 0; t_ < 15; t_++)                                   \
            bd[t_] = (dv_ < bd[t_+1]) ? bd[t_+1] : ((dv_ < bd[t_]) ? dv_ : bd[t_]); \
        bd[15] = (dv_ < bd[15]) ? dv_ : bd[15];                           \
    }                                                                     \
} while (0)

// ---------------- brute-force KNN (3-phase, packed-pair scan): 4 threads/query ----------------
#define NPAIR 2048
#define KQ 128                   // queries per block
#define KTH 512                  // threads per block
#define KNN_SMEM (65536 + 32768 + 1024 + 512)
__global__ __launch_bounds__(KTH) void knn_both(const float* __restrict__ xyz1,
                                                const float* __restrict__ xyz2)
{
    extern __shared__ char smem_raw[];
    u64* sX = (u64*)smem_raw;                 // 2048 pairs
    u64* sY = sX + NPAIR;
    u64* sZ = sY + NPAIR;
    u64* sS = sZ + NPAIR;
    char* tail = (char*)(sS + NPAIR);
    float* svals = (float*)tail;                      // [128][64]  (phase 1.5 only)
    int*   sless = (int*)tail;                        // [128][16]  (phase 2; overlays svals)
    int*   seq   = (int*)(tail + 8192);               // [128][32]  (phase 2; overlays svals)
    int*   scnt  = (int*)(tail + 32768);              // [128][2]
    float* sthr  = (float*)(tail + 32768 + 1024);     // [128]

    int which = blockIdx.z;          // 0: cand=xyz2 -> g_idx1, 1: cand=xyz1 -> g_idx2
    const float* cxyz = which ? xyz1 : xyz2;
    int* out = which ? g_idx2 : g_idx1;
    int b = blockIdx.y;
    const float* cb = cxyz + b*3*NPT;
    int tid = threadIdx.x;
    for (int idx = tid; idx < NPAIR; idx += KTH) {
        int i0 = idx*2, i1 = i0+1;
        float x0 = cb[i0],        x1 = cb[i1];
        float y0 = cb[NPT+i0],    y1 = cb[NPT+i1];
        float z0 = cb[2*NPT+i0],  z1 = cb[2*NPT+i1];
        float s0 = __fadd_rn(__fadd_rn(__fmul_rn(x0,x0), __fmul_rn(y0,y0)), __fmul_rn(z0,z0));
        float s1 = __fadd_rn(__fadd_rn(__fmul_rn(x1,x1), __fmul_rn(y1,y1)), __fmul_rn(z1,z1));
        u64 t;
        PACK2(t, x0, x1); sX[idx] = t;
        PACK2(t, y0, y1); sY[idx] = t;
        PACK2(t, z0, z1); sZ[idx] = t;
        PACK2(t, s0, s1); sS[idx] = t;
    }
    if (tid < 2*KQ) scnt[tid] = 0;
    __syncthreads();

    int ql = tid >> 2, part = tid & 3;
    int n = blockIdx.x * KQ + ql;
    const float* qb = xyz1 + b*3*NPT;
    float qx = qb[n], qy = qb[NPT+n], qz = qb[2*NPT+n];
    float q2 = __fadd_rn(__fadd_rn(__fmul_rn(qx,qx), __fmul_rn(qy,qy)), __fmul_rn(qz,qz));
    u64 qxp, qyp, qzp, q2p, m2p;
    PACK2(qxp, qx, qx); PACK2(qyp, qy, qy); PACK2(qzp, qz, qz);
    PACK2(q2p, q2, q2); PACK2(m2p, -2.0f, -2.0f);

    // Phase 1: sorted-descending value list + 4-deep shift queue
    float bd[16];
#pragma unroll
    for (int t = 0; t < 16; t++) bd[t] = 3.0e38f;
    float gate = 3.0e38f;
    float tq0 = 0.f, tq1 = 0.f, tq2 = 0.f, tq3 = 0.f;
    int cnt = 0;

#pragma unroll 2
    for (int j = 0; j < 512; j++) {
        int pi = (j << 2) | part;                  // pair index; candidates 2pi, 2pi+1
        u64 X = sX[pi], Y = sY[pi], Z = sZ[pi], S = sS[pi];
        u64 cr; MUL2(cr, qxp, X); FMA2(cr, qyp, Y); FMA2(cr, qzp, Z);
        u64 dd; ADD2(dd, q2p, S); FMA2(dd, m2p, cr);
        float d0, d1; UNPK2(d0, d1, dd);
        if (d0 <= gate) { tq3 = tq2; tq2 = tq1; tq1 = tq0; tq0 = d0; cnt++; }
        if (d1 <= gate) { tq3 = tq2; tq2 = tq1; tq1 = tq0; tq0 = d1; cnt++; }
        if (__ballot_sync(0xffffffffu, cnt >= 3)) {
            if (cnt >= 1) INSERT16(tq0);
            if (cnt >= 2) INSERT16(tq1);
            if (cnt >= 3) INSERT16(tq2);
            if (cnt >= 4) INSERT16(tq3);
            cnt = 0;
            float w = bd[0];
            w = fminf(w, __shfl_xor_sync(0xffffffffu, w, 1));
            w = fminf(w, __shfl_xor_sync(0xffffffffu, w, 2));
            gate = w;
        }
    }
    if (cnt >= 1) INSERT16(tq0);
    if (cnt >= 2) INSERT16(tq1);
    if (cnt >= 3) INSERT16(tq2);
    if (cnt >= 4) INSERT16(tq3);

#pragma unroll
    for (int r = 0; r < 16; r++) svals[ql*64 + part*16 + r] = bd[15-r];
    __syncthreads();

    // Phase 1.5: 4-list merge -> thr (one thread per query)
    if (part == 0) {
        const float* L = svals + ql*64;
        int p0 = 0, p1 = 0, p2 = 0, p3 = 0;
        float last = 0.f;
        for (int r = 0; r < 16; r++) {
            float v0 = L[p0], v1 = L[16+p1], v2 = L[32+p2], v3 = L[48+p3];
            float m;
            if (v0 <= v1 && v0 <= v2 && v0 <= v3) { m = v0; p0++; }
            else if (v1 <= v2 && v1 <= v3)        { m = v1; p1++; }
            else if (v2 <= v3)                    { m = v2; p2++; }
            else                                  { m = v3; p3++; }
            last = m;
        }
        sthr[ql] = last;
    }
    __syncthreads();     // after this, svals is dead -> sless/seq may overlay it

    // Phase 2: rescan with identical packed arithmetic; collect indices
    float thr = sthr[ql];
#pragma unroll 2
    for (int j = 0; j < 512; j++) {
        int pi = (j << 2) | part;
        u64 X = sX[pi], Y = sY[pi], Z = sZ[pi], S = sS[pi];
        u64 cr; MUL2(cr, qxp, X); FMA2(cr, qyp, Y); FMA2(cr, qzp, Z);
        u64 dd; ADD2(dd, q2p, S); FMA2(dd, m2p, cr);
        float d0, d1; UNPK2(d0, d1, dd);
        if (d0 <= thr) {
            int i = pi*2;
            if (d0 < thr) {
                int pos = atomicAdd(&scnt[ql*2 + 0], 1);
                sless[ql*16 + pos] = i;            // provably pos <= 14
            } else {
                int pos = atomicAdd(&scnt[ql*2 + 1], 1);
                if (pos < 32) seq[ql*32 + pos] = i;
            }
        }
        if (d1 <= thr) {
            int i = pi*2 + 1;
            if (d1 < thr) {
                int pos = atomicAdd(&scnt[ql*2 + 0], 1);
                sless[ql*16 + pos] = i;
            } else {
                int pos = atomicAdd(&scnt[ql*2 + 1], 1);
                if (pos < 32) seq[ql*32 + pos] = i;
            }
        }
    }
    __syncthreads();

    // Finalize: sort the <thr indices, append `need` smallest ==thr indices
    if (part == 0) {
        int nl = scnt[ql*2 + 0];
        int ne = scnt[ql*2 + 1]; if (ne > 32) ne = 32;
        int need = 16 - nl;
        int* Ls = sless + ql*16;
        for (int a = 1; a < nl; a++) {
            int v = Ls[a]; int bp = a;
            while (bp > 0 && Ls[bp-1] > v) { Ls[bp] = Ls[bp-1]; bp--; }
            Ls[bp] = v;
        }
        int* Es = seq + ql*32;
        int base = (b*NPT + n)*16;
        for (int r = 0; r < nl; r++) out[base + r] = Ls[r];
        for (int r = 0; r < need; r++) {
            int mi = 0x7fffffff, mp = 0;
            for (int a = 0; a < ne; a++) if (Es[a] < mi) { mi = Es[a]; mp = a; }
            Es[mp] = 0x7fffffff;
            out[base + nl + r] = mi;
        }
    }
}

// ---------------- group1 (f32x2 packed, smem weights, per-group named barriers) ----------------
#define GSZ1 2784
#define G1_SMEM ((15248 + 4*GSZ1)*4)
__global__ __launch_bounds__(256, 2) void group1_kernel(const float* __restrict__ wm2,
                                                        const float* __restrict__ bpos1,
                                                        int groups_total, int iters)
{
    extern __shared__ float sm[];
    float* s_wv1  = sm;                 // 8448  [o][132]
    float* s_wk1  = s_wv1 + 8448;       // 4352  [o][68]
    float* s_wm1T = s_wk1 + 4352;       // 1024  [op][16] (negated)
    float* s_WmqT = s_wm1T + 1024;      // 1024  [c][16]
    float* s_wp1T = s_WmqT + 1024;      // 320   [r][64]
    float* s_wm2  = s_wp1T + 320;       // 16
    float* s_b1   = s_wm2  + 16;        // 64
    float* s_grp0 = s_b1   + 64;

    int tid = threadIdx.x;
    for (int i = tid; i < 8448; i += 256) s_wv1[i] = g_wv1R[i];
    for (int i = tid; i < 4352; i += 256) s_wk1[i] = g_wk1R[i];
    for (int i = tid; i < 1024; i += 256) { s_wm1T[i] = g_wm1T[i]; s_WmqT[i] = g_WmqT[i]; }
    for (int i = tid; i < 320;  i += 256) s_wp1T[i] = g_wp1T[i];
    if (tid < 16) s_wm2[tid] = wm2[tid];
    if (tid < 64) s_b1[tid] = bpos1[tid];

    int g = tid >> 6, o = tid & 63;
    float* snb  = s_grp0 + g*GSZ1;      // [64][20], later reused for k
    float* svpe = snb  + 64*NBST;       // [64][20]
    float* spts = svpe + 64*NBST;       // 64
    float* spos = spts + 64;            // [5][16]
    float* smq  = spos + 80;            // 16
    float* slog = smq  + 16;            // 16
    float* sfn2 = slog + 16;            // 16 (cross-warp partials)
    float* smqp = sfn2 + 16;            // 16
    int*   sidx = (int*)(smqp + 16);    // 16
    int gg = blockIdx.x * 4 + g;
    int sU = o & 15, qt = o >> 4;       // distributed fn2/mq assignment
    __syncthreads();                    // weights visible to all groups

    for (int it = 0; it < iters; it++) {
        int p = gg + it * groups_total;
        bool active = p < NPTS;
        int b = p >> 12;

        if (active) {
            if (o < 16) sidx[o] = g_idx1[(p<<4) + o];
            spts[o] = g_f1T[(p<<6) + o];
        }
        GBAR(g);
        if (active) {
#pragma unroll
            for (int s = 0; s < 16; s++) {
                int id = sidx[s];
                snb[o*NBST + s] = g_f2T[(((b<<12) + id)<<6) + o];
            }
        }
        GBAR(g);

        // vbase = wv1[o][0:64] . pts   (scalar horizontal dot)
        float vbase = 0.f;
        {
            const float4* wr4 = (const float4*)(s_wv1 + o*WV1S);
            const float4* pt4 = (const float4*)spts;
#pragma unroll 4
            for (int c4 = 0; c4 < 16; c4++) {
                float4 wv = wr4[c4]; float4 pv = pt4[c4];
                vbase += wv.x*pv.x; vbase += wv.y*pv.y;
                vbase += wv.z*pv.z; vbase += wv.w*pv.w;
            }
        }

        // distributed fn2 / mq: 4 threads per neighbor s, 16 channels each
        {
            float fn2p = 0.f, mqp = 0.f;
#pragma unroll
            for (int cc = 0; cc < 16; cc++) {
                int c = qt*16 + cc;
                float pv = spts[c];
                float t = pv - snb[c*NBST + sU];
                fn2p = __fmaf_rn(t, t, fn2p);
                mqp  = __fmaf_rn(s_WmqT[c*16 + sU], pv, mqp);
            }
            fn2p += __shfl_xor_sync(0xffffffffu, fn2p, 16);
            mqp  += __shfl_xor_sync(0xffffffffu, mqp, 16);
            if (o >= 32 && o < 48) { sfn2[sU] = fn2p; smqp[sU] = mqp; }
            GBAR(g);
            if (active && o < 16) {
                int s = o; int id = sidx[s];
                const float* q3 = g_x1T + p*3;
                const float* c3 = g_x2T + ((b<<12) + id)*3;
                float dx = q3[0]-c3[0], dy = q3[1]-c3[1], dz = q3[2]-c3[2];
                spos[0*16+s] = sqrtf(fn2p + sfn2[s]);
                spos[1*16+s] = sqrtf(dx*dx + dy*dy + dz*dz);
                spos[2*16+s] = dx; spos[3*16+s] = dy; spos[4*16+s] = dz;
                smq[s] = mqp + smqp[s];
            }
        }
        GBAR(g);

        // v[s] packed: va[k] = (v[2k], v[2k+1])
        u64 va[8];
        {
            u64 vb2; PACK2(vb2, vbase, vbase);
#pragma unroll
            for (int k = 0; k < 8; k++) va[k] = vb2;
        }
#pragma unroll
        for (int jj = 0; jj < 3; jj++) {
            float wj = s_wv1[o*WV1S + 128 + jj];
            u64 ww; PACK2(ww, wj, wj);
            ACC16P(va, ww, spos + (2+jj)*16);
        }
        {
            const float4* wn4 = (const float4*)(s_wv1 + o*WV1S + 64);
#pragma unroll 4
            for (int c4 = 0; c4 < 16; c4++) {
                float4 wv = wn4[c4];
                u64 w0, w1, w2, w3;
                PACK2(w0, wv.x, wv.x); PACK2(w1, wv.y, wv.y);
                PACK2(w2, wv.z, wv.z); PACK2(w3, wv.w, wv.w);
                ACC16P(va, w0, snb + (c4*4+0)*NBST);
                ACC16P(va, w1, snb + (c4*4+1)*NBST);
                ACC16P(va, w2, snb + (c4*4+2)*NBST);
                ACC16P(va, w3, snb + (c4*4+3)*NBST);
            }
        }
        // pos_enc packed
        u64 pea[8];
        {
            float bb = s_b1[o];
            u64 bb2; PACK2(bb2, bb, bb);
#pragma unroll
            for (int k = 0; k < 8; k++) pea[k] = bb2;
        }
#pragma unroll
        for (int r = 0; r < 5; r++) {
            float wr = s_wp1T[r*64 + o];
            u64 ww; PACK2(ww, wr, wr);
            ACC16P(pea, ww, spos + r*16);
        }
        // svpe = v + pe
        {
            ulonglong2* dst = (ulonglong2*)(svpe + o*NBST);
#pragma unroll
            for (int k = 0; k < 4; k++) {
                u64 lo, hi;
                ADD2(lo, va[2*k],   pea[2*k]);
                ADD2(hi, va[2*k+1], pea[2*k+1]);
                ulonglong2 w2v; w2v.x = lo; w2v.y = hi;
                dst[k] = w2v;
            }
        }
        GBAR(g);

        // k[s] packed
        u64 ka[8];
#pragma unroll
        for (int k = 0; k < 8; k++) ka[k] = 0ull;
        {
            const float4* wk4 = (const float4*)(s_wk1 + o*W64S);
#pragma unroll 4
            for (int c4 = 0; c4 < 16; c4++) {
                float4 wv = wk4[c4];
                u64 w0, w1, w2, w3;
                PACK2(w0, wv.x, wv.x); PACK2(w1, wv.y, wv.y);
                PACK2(w2, wv.z, wv.z); PACK2(w3, wv.w, wv.w);
                ACC16P(ka, w0, svpe + (c4*4+0)*NBST);
                ACC16P(ka, w1, svpe + (c4*4+1)*NBST);
                ACC16P(ka, w2, svpe + (c4*4+2)*NBST);
                ACC16P(ka, w3, svpe + (c4*4+3)*NBST);
            }
        }
        {
            ulonglong2* dst = (ulonglong2*)(snb + o*NBST);   // snb reused as k buffer
#pragma unroll
            for (int k = 0; k < 4; k++) {
                ulonglong2 w2v; w2v.x = ka[2*k]; w2v.y = ka[2*k+1];
                dst[k] = w2v;
            }
        }
        GBAR(g);

        // attn logits: h = relu(mq - wm1 @ k)  (wm1 pre-negated -> pure FMA2 accumulate)
        {
            int j = o & 15, sb = o >> 4;
            float mqj = smq[j];
            u64 hp0, hp1;
            PACK2(hp0, mqj, mqj); PACK2(hp1, mqj, mqj);
#pragma unroll 8
            for (int op = 0; op < 64; op++) {
                float w = s_wm1T[op*16 + j];     // = -wm1
                u64 ww; PACK2(ww, w, w);
                const ulonglong2* nbp = (const ulonglong2*)(snb + op*NBST + sb*4);
                ulonglong2 nbv = nbp[0];
                FMA2(hp0, ww, nbv.x);
                FMA2(hp1, ww, nbv.y);
            }
            float h0, h1, h2, h3;
            UNPK2(h0, h1, hp0); UNPK2(h2, h3, hp1);
            float wj = s_wm2[j];
            float hq[4] = {h0, h1, h2, h3};
#pragma unroll
            for (int ss = 0; ss < 4; ss++) {
                float part = wj * fmaxf(hq[ss], 0.f);
                part += __shfl_xor_sync(0xffffffffu, part, 1);
                part += __shfl_xor_sync(0xffffffffu, part, 2);
                part += __shfl_xor_sync(0xffffffffu, part, 4);
                part += __shfl_xor_sync(0xffffffffu, part, 8);
                if (j == 0) slog[sb*4 + ss] = part;
            }
        }
        GBAR(g);

        // softmax + weighted sum + leaky
        float v[16];
#pragma unroll
        for (int k = 0; k < 8; k++) UNPK2(v[2*k], v[2*k+1], va[k]);
        float mx = -3.0e38f;
#pragma unroll
        for (int s = 0; s < 16; s++) mx = fmaxf(mx, slog[s]);
        float sum = 0.f, outv = 0.f;
#pragma unroll
        for (int s = 0; s < 16; s++) {
            float e = __expf(slog[s] - mx);
            sum += e; outv += e * v[s];
        }
        outv /= sum;
        outv = (outv >= 0.f) ? outv : 0.1f*outv;
        if (active) g_p2nT[(p<<6) + o] = outv;
        GBAR(g);
    }
}

// ---------------- group2 (f32x2 packed, smem weights, per-group named barriers) ----------------
#define G2_SMEM (24384*4)
__global__ __launch_bounds__(256, 2) void group2_kernel(const float* __restrict__ bpos2,
                                                        float* __restrict__ outp,
                                                        int groups_total, int iters)
{
    extern __shared__ float sm[];
    float* s_wq2  = sm;                 // 4352 [o][68]
    float* s_wk2  = s_wq2 + 4352;       // 4352
    float* s_wv2  = s_wk2 + 4352;       // 4352
    float* s_wp2T = s_wv2 + 4352;       // 256
    float* s_b2   = s_wp2T + 256;       // 64
    float* s_grp0 = s_b2   + 64;

    int tid = threadIdx.x;
    for (int i = tid; i < 4352; i += 256) {
        s_wq2[i] = g_wq2R[i]; s_wk2[i] = g_wk2R[i]; s_wv2[i] = g_wv2R[i];
    }
    for (int i = tid; i < 256; i += 256) s_wp2T[i] = g_wp2T[i];
    if (tid < 64) s_b2[tid] = bpos2[tid];

    const int GSZ = 2752;
    int g = tid >> 6, o = tid & 63;
    float* snb  = s_grp0 + g*GSZ;       // [64][20]
    float* stmp = snb  + 64*NBST;       // [64][20]
    float* spts = stmp + 64*NBST;       // 64
    float* spos = spts + 64;            // [4][16]
    float* slog = spos + 64;            // 16 (scratch)
    float* sred = slog + 16;            // 32
    int*   sidx = (int*)(sred + 32);    // 16
    int gg = blockIdx.x * 4 + g;
    __syncthreads();                    // weights visible to all groups

    for (int it = 0; it < iters; it++) {
        int p = gg + it * groups_total;
        bool active = p < NPTS;
        int b = p >> 12, n = p & (NPT-1);

        if (active) {
            if (o < 16) sidx[o] = g_idx2[(p<<4) + o];
            spts[o] = g_p2nT[(p<<6) + o];
        }
        GBAR(g);
        if (active) {
#pragma unroll
            for (int s = 0; s < 16; s++) {
                int id = sidx[s];
                snb[o*NBST + s] = g_p2nT[(((b<<12) + id)<<6) + o];
            }
        }
        GBAR(g);

        float q = 0.f;
        {
            const float4* wr4 = (const float4*)(s_wq2 + o*W64S);
            const float4* pt4 = (const float4*)spts;
#pragma unroll 4
            for (int c4 = 0; c4 < 16; c4++) {
                float4 wv = wr4[c4]; float4 pv = pt4[c4];
                q += wv.x*pv.x; q += wv.y*pv.y; q += wv.z*pv.z; q += wv.w*pv.w;
            }
        }
        q *= 0.125f;   // 64^-0.5

        if (active && o < 16) {
            int s = o; int id = sidx[s];
            const float* q3 = g_x1T + p*3;
            const float* c3 = g_x1T + ((b<<12) + id)*3;
            float dx = q3[0]-c3[0], dy = q3[1]-c3[1], dz = q3[2]-c3[2];
            spos[0*16+s] = dx; spos[1*16+s] = dy; spos[2*16+s] = dz;
            spos[3*16+s] = sqrtf(dx*dx + dy*dy + dz*dz);
        }
        GBAR(g);

        // pos_enc packed
        u64 pea[8];
        {
            float bb = s_b2[o];
            u64 bb2; PACK2(bb2, bb, bb);
#pragma unroll
            for (int k = 0; k < 8; k++) pea[k] = bb2;
        }
#pragma unroll
        for (int r = 0; r < 4; r++) {
            float wr = s_wp2T[r*64 + o];
            u64 ww; PACK2(ww, wr, wr);
            ACC16P(pea, ww, spos + r*16);
        }
        // stmp = nb + pe
        {
            const ulonglong2* src = (const ulonglong2*)(snb + o*NBST);
            ulonglong2* dst = (ulonglong2*)(stmp + o*NBST);
#pragma unroll
            for (int k = 0; k < 4; k++) {
                ulonglong2 nbv = src[k];
                u64 lo, hi;
                ADD2(lo, nbv.x, pea[2*k]);
                ADD2(hi, nbv.y, pea[2*k+1]);
                ulonglong2 w2v; w2v.x = lo; w2v.y = hi;
                dst[k] = w2v;
            }
        }
        GBAR(g);

        // k = wk2 @ tmp ; v = wv2 @ nb  (packed)
        u64 ka[8], vva[8];
#pragma unroll
        for (int k = 0; k < 8; k++) { ka[k] = 0ull; vva[k] = 0ull; }
        {
            const float4* wk4 = (const float4*)(s_wk2 + o*W64S);
            const float4* wv4 = (const float4*)(s_wv2 + o*W64S);
#pragma unroll 2
            for (int c4 = 0; c4 < 16; c4++) {
                float4 a = wk4[c4];
                float4 c = wv4[c4];
                u64 a0, a1, a2, a3, c0, c1, c2, c3;
                PACK2(a0, a.x, a.x); PACK2(a1, a.y, a.y);
                PACK2(a2, a.z, a.z); PACK2(a3, a.w, a.w);
                PACK2(c0, c.x, c.x); PACK2(c1, c.y, c.y);
                PACK2(c2, c.z, c.z); PACK2(c3, c.w, c.w);
                ACC16P(ka,  a0, stmp + (c4*4+0)*NBST);
                ACC16P(vva, c0, snb  + (c4*4+0)*NBST);
                ACC16P(ka,  a1, stmp + (c4*4+1)*NBST);
                ACC16P(vva, c1, snb  + (c4*4+1)*NBST);
                ACC16P(ka,  a2, stmp + (c4*4+2)*NBST);
                ACC16P(vva, c2, snb  + (c4*4+2)*NBST);
                ACC16P(ka,  a3, stmp + (c4*4+3)*NBST);
                ACC16P(vva, c3, snb  + (c4*4+3)*NBST);
            }
        }
        float kk[16], vv[16];
#pragma unroll
        for (int k = 0; k < 8; k++) {
            UNPK2(kk[2*k], kk[2*k+1], ka[k]);
            UNPK2(vv[2*k], vv[2*k+1], vva[k]);
        }

        // logits[s] = sum_o q[o]*k[o][s] : warp reduce then cross-warp via smem
#pragma unroll
        for (int s = 0; s < 16; s++) {
            float x = q * kk[s];
            x += __shfl_xor_sync(0xffffffffu, x, 16);
            x += __shfl_xor_sync(0xffffffffu, x, 8);
            x += __shfl_xor_sync(0xffffffffu, x, 4);
            x += __shfl_xor_sync(0xffffffffu, x, 2);
            x += __shfl_xor_sync(0xffffffffu, x, 1);
            kk[s] = x;
        }
        if ((o & 31) == 0) {
#pragma unroll
            for (int s = 0; s < 16; s++) sred[(o>>5)*16 + s] = kk[s];
        }
        GBAR(g);

        float lg[16];
#pragma unroll
        for (int s = 0; s < 16; s++) lg[s] = sred[s] + sred[16+s];
        float mx = -3.0e38f;
#pragma unroll
        for (int s = 0; s < 16; s++) mx = fmaxf(mx, lg[s]);
        float sum = 0.f, outv = 0.f;
#pragma unroll
        for (int s = 0; s < 16; s++) {
            float e = __expf(lg[s] - mx);
            sum += e; outv += e * vv[s];
        }
        outv /= sum;
        outv = (outv >= 0.f) ? outv : 0.1f*outv;
        if (active) outp[(b*64 + o)*NPT + n] = outv;
        GBAR(g);
    }
}

// ---------------- launch ----------------
extern "C" void kernel_launch(void* const* d_in, const int* in_sizes, int n_in,
                              void* d_out, int out_size)
{
    const float* xyz1  = (const float*)d_in[0];
    const float* feat1 = (const float*)d_in[1];
    const float* xyz2  = (const float*)d_in[2];
    const float* feat2 = (const float*)d_in[3];
    const float* wq1   = (const float*)d_in[4];
    const float* wk1   = (const float*)d_in[5];
    const float* wv1   = (const float*)d_in[6];
    const float* wm1   = (const float*)d_in[7];
    const float* wm2   = (const float*)d_in[8];
    const float* wp1   = (const float*)d_in[9];
    const float* b1    = (const float*)d_in[10];
    const float* wq2   = (const float*)d_in[11];
    const float* wk2   = (const float*)d_in[12];
    const float* wv2   = (const float*)d_in[13];
    const float* wp2   = (const float*)d_in[14];
    const float* b2    = (const float*)d_in[15];
    float* out = (float*)d_out;

    cudaFuncSetAttribute(knn_both,      cudaFuncAttributeMaxDynamicSharedMemorySize, KNN_SMEM);
    cudaFuncSetAttribute(group1_kernel, cudaFuncAttributeMaxDynamicSharedMemorySize, G1_SMEM);
    cudaFuncSetAttribute(group2_kernel, cudaFuncAttributeMaxDynamicSharedMemorySize, G2_SMEM);

    const int GRID = 296;                 // 2 blocks/SM on 148 SMs
    const int GROUPS = GRID * 4;          // 1184 point-groups
    const int ITERS = (NPTS + GROUPS - 1) / GROUPS;   // 14

    // launch order: knn depends only on raw xyz; group1 lands at index 3 (profiled slot)
    transpose_feat<<<dim3(64, B4, 2), dim3(64, 8)>>>(feat1, feat2);                 // 0
    transpose_xyz_prep<<<dim3(64, 1, 2), 256>>>(xyz1, xyz2, wq1, wk1, wv1, wm1,
                                                wp1, wq2, wk2, wv2, wp2);           // 1
    knn_both<<<dim3(NPT/KQ, B4, 2), KTH, KNN_SMEM>>>(xyz1, xyz2);                   // 2
    group1_kernel<<<GRID, 256, G1_SMEM>>>(wm2, b1, GROUPS, ITERS);                  // 3 <- profiled
    group2_kernel<<<GRID, 256, G2_SMEM>>>(b2, out, GROUPS, ITERS);                  // 4
}

// round 17
// speedup vs baseline: 1.2414x; 1.1743x over previous
#include <cuda_runtime.h>
#include <math.h>

#define B4 4
#define NPT 4096
#define CH 64
#define KNN 16
#define NPTS (B4*NPT)          // 16384
#define NBST 20                // padded row stride for [64][16] smem tiles
#define WV1S 132               // row stride for wv1 [64][132] (131 used)
#define W64S 68                // row stride for 64x64 weights

typedef unsigned long long u64;

// ---------------- f32x2 packed math (FFMA2 — only reachable via PTX) ----------------
#define FMA2(acc, A_, B_) asm("fma.rn.f32x2 %0, %1, %2, %0;" : "+l"(acc) : "l"(A_), "l"(B_))
#define MUL2(out, A_, B_) asm("mul.rn.f32x2 %0, %1, %2;" : "=l"(out) : "l"(A_), "l"(B_))
#define ADD2(out, A_, B_) asm("add.rn.f32x2 %0, %1, %2;" : "=l"(out) : "l"(A_), "l"(B_))
#define PACK2(out, lo, hi) asm("mov.b64 %0, {%1, %2};" : "=l"(out) : "f"(lo), "f"(hi))
#define UNPK2(lo, hi, in) asm("mov.b64 {%0, %1}, %2;" : "=f"(lo), "=f"(hi) : "l"(in))

// per-group named barrier: 64 threads, barrier id = group+1
#define GBAR(gid) asm volatile("bar.sync %0, 64;" :: "r"((gid)+1) : "memory")

// packed 16-wide accumulate: Ac = u64[8] accumulators, Ww = packed (w,w), Bp = 16B-aligned 16-float row
#define ACC16P(Ac, Ww, Bp) do {                                          \
    const ulonglong2* p_ = (const ulonglong2*)(Bp);                      \
    ulonglong2 d0_ = p_[0], d1_ = p_[1], d2_ = p_[2], d3_ = p_[3];       \
    FMA2(Ac[0], Ww, d0_.x); FMA2(Ac[1], Ww, d0_.y);                      \
    FMA2(Ac[2], Ww, d1_.x); FMA2(Ac[3], Ww, d1_.y);                      \
    FMA2(Ac[4], Ww, d2_.x); FMA2(Ac[5], Ww, d2_.y);                      \
    FMA2(Ac[6], Ww, d3_.x); FMA2(Ac[7], Ww, d3_.y);                      \
} while (0)

// ---------------- scratch (device globals; no allocation) ----------------
__device__ float g_f1T[B4*NPT*CH];
__device__ float g_f2T[B4*NPT*CH];
__device__ float g_x1T[B4*NPT*3];
__device__ float g_x2T[B4*NPT*3];
__device__ float g_p2nT[B4*NPT*CH];
__device__ int   g_idx1[B4*NPT*KNN];
__device__ int   g_idx2[B4*NPT*KNN];
__device__ float g_wv1R[64*WV1S];   // [o][132]
__device__ float g_Wmk1T[64*16];    // [c][16] = -(wm1 @ wk1)^T  (fused, negated)
__device__ float g_WmqT[64*16];     // [c][16] =  (wm1 @ wq1)^T
__device__ float g_wp1T[5*64];
__device__ float g_wq2R[64*W64S];   // [o][68]
__device__ float g_wv2R[64*W64S];   // [o][68]
__device__ float g_wk2C[64*W64S];   // [c][68]  (column layout for q^T wk2)
__device__ float g_wp2T[4*64];

// ---------------- transposes (merged: z selects tensor) ----------------
__global__ void transpose_feat(const float* __restrict__ in1, const float* __restrict__ in2)
{
    __shared__ float tile[64][65];
    int which = blockIdx.z;
    const float* in = which ? in2 : in1;
    float* out = which ? g_f2T : g_f1T;
    int b = blockIdx.y, n0 = blockIdx.x * 64;
    int tx = threadIdx.x, ty = threadIdx.y;
    for (int c = ty; c < 64; c += 8)
        tile[c][tx] = in[(b*64 + c)*NPT + n0 + tx];
    __syncthreads();
    for (int nn = ty; nn < 64; nn += 8)
        out[(b*NPT + n0 + nn)*64 + tx] = tile[tx][nn];
}

// transpose_xyz + (block x==0,z==0 only) weight prep
__global__ void transpose_xyz_prep(const float* __restrict__ in1, const float* __restrict__ in2,
                                   const float* __restrict__ wq1, const float* __restrict__ wk1,
                                   const float* __restrict__ wv1, const float* __restrict__ wm1,
                                   const float* __restrict__ wp1, const float* __restrict__ wq2,
                                   const float* __restrict__ wk2, const float* __restrict__ wv2,
                                   const float* __restrict__ wp2)
{
    int which = blockIdx.z;
    const float* in = which ? in2 : in1;
    float* out = which ? g_x2T : g_x1T;
    int i = blockIdx.x * blockDim.x + threadIdx.x;
    if (i < B4*NPT) {
        int b = i >> 12, n = i & (NPT-1);
        out[i*3+0] = in[b*3*NPT + n];
        out[i*3+1] = in[b*3*NPT + NPT + n];
        out[i*3+2] = in[b*3*NPT + 2*NPT + n];
    }
    if (blockIdx.x == 0 && blockIdx.z == 0) {
        int t = threadIdx.x;
        for (int k = t; k < 64*WV1S; k += 256) {
            int o = k / WV1S, c = k % WV1S;
            g_wv1R[k] = (c < 131) ? wv1[o*131 + c] : 0.f;
        }
        for (int k = t; k < 64*W64S; k += 256) {
            int o = k / W64S, c = k % W64S;
            g_wq2R[k] = (c < 64) ? wq2[o*64+c] : 0.f;
            g_wv2R[k] = (c < 64) ? wv2[o*64+c] : 0.f;
            // g_wk2C: row index is c, inner is o
            int cc = k / W64S, oo = k % W64S;
            g_wk2C[k] = (oo < 64) ? wk2[oo*64+cc] : 0.f;
        }
        for (int k = t; k < 64*5;  k += 256) { int o = k/5,  r = k%5;  g_wp1T[r*64+o] = wp1[k]; }
        for (int k = t; k < 64*4;  k += 256) { int o = k/4,  r = k%4;  g_wp2T[r*64+o] = wp2[k]; }
        // WmqT[c*16+j] = sum_o wm1[j][o] * wq1[o][c]
        // Wmk1T[c*16+j] = -sum_o wm1[j][o] * wk1[o][c]   (negated for pure-FMA logits)
        for (int k = t; k < 64*16; k += 256) {
            int c = k/16, j = k%16;
            float s1 = 0.f, s2 = 0.f;
            for (int o = 0; o < 64; o++) {
                s1 += wm1[j*64+o] * wq1[o*64+c];
                s2 += wm1[j*64+o] * wk1[o*64+c];
            }
            g_WmqT[c*16+j] = s1;
            g_Wmk1T[c*16+j] = -s2;
        }
    }
}

// sorted-descending insert of d into bd[16] (bd[0]=worst), guarded by d<bd[0]
#define INSERT16(d_) do {                                                 \
    float dv_ = (d_);                                                     \
    if (dv_ < bd[0]) {                                                    \
        _Pragma("unroll")                                                 \
        for (int t_ = 0; t_ < 15; t_++)                                   \
            bd[t_] = (dv_ < bd[t_+1]) ? bd[t_+1] : ((dv_ < bd[t_]) ? dv_ : bd[t_]); \
        bd[15] = (dv_ < bd[15]) ? dv_ : bd[15];                           \
    }                                                                     \
} while (0)

// ---------------- brute-force KNN (3-phase, packed-pair scan): 4 threads/query ----------------
#define NPAIR 2048
#define KQ 128                   // queries per block
#define KTH 512                  // threads per block
#define KNN_SMEM (65536 + 32768 + 1024 + 512)
__global__ __launch_bounds__(KTH) void knn_both(const float* __restrict__ xyz1,
                                                const float* __restrict__ xyz2)
{
    extern __shared__ char smem_raw[];
    u64* sX = (u64*)smem_raw;                 // 2048 pairs
    u64* sY = sX + NPAIR;
    u64* sZ = sY + NPAIR;
    u64* sS = sZ + NPAIR;
    char* tail = (char*)(sS + NPAIR);
    float* svals = (float*)tail;                      // [128][64]  (phase 1.5 only)
    int*   sless = (int*)tail;                        // [128][16]  (phase 2; overlays svals)
    int*   seq   = (int*)(tail + 8192);               // [128][32]  (phase 2; overlays svals)
    int*   scnt  = (int*)(tail + 32768);              // [128][2]
    float* sthr  = (float*)(tail + 32768 + 1024);     // [128]

    int which = blockIdx.z;          // 0: cand=xyz2 -> g_idx1, 1: cand=xyz1 -> g_idx2
    const float* cxyz = which ? xyz1 : xyz2;
    int* out = which ? g_idx2 : g_idx1;
    int b = blockIdx.y;
    const float* cb = cxyz + b*3*NPT;
    int tid = threadIdx.x;
    for (int idx = tid; idx < NPAIR; idx += KTH) {
        int i0 = idx*2, i1 = i0+1;
        float x0 = cb[i0],        x1 = cb[i1];
        float y0 = cb[NPT+i0],    y1 = cb[NPT+i1];
        float z0 = cb[2*NPT+i0],  z1 = cb[2*NPT+i1];
        float s0 = __fadd_rn(__fadd_rn(__fmul_rn(x0,x0), __fmul_rn(y0,y0)), __fmul_rn(z0,z0));
        float s1 = __fadd_rn(__fadd_rn(__fmul_rn(x1,x1), __fmul_rn(y1,y1)), __fmul_rn(z1,z1));
        u64 t;
        PACK2(t, x0, x1); sX[idx] = t;
        PACK2(t, y0, y1); sY[idx] = t;
        PACK2(t, z0, z1); sZ[idx] = t;
        PACK2(t, s0, s1); sS[idx] = t;
    }
    if (tid < 2*KQ) scnt[tid] = 0;
    __syncthreads();

    int ql = tid >> 2, part = tid & 3;
    int n = blockIdx.x * KQ + ql;
    const float* qb = xyz1 + b*3*NPT;
    float qx = qb[n], qy = qb[NPT+n], qz = qb[2*NPT+n];
    float q2 = __fadd_rn(__fadd_rn(__fmul_rn(qx,qx), __fmul_rn(qy,qy)), __fmul_rn(qz,qz));
    u64 qxp, qyp, qzp, q2p, m2p;
    PACK2(qxp, qx, qx); PACK2(qyp, qy, qy); PACK2(qzp, qz, qz);
    PACK2(q2p, q2, q2); PACK2(m2p, -2.0f, -2.0f);

    // Phase 1: sorted-descending value list + 4-deep shift queue
    float bd[16];
#pragma unroll
    for (int t = 0; t < 16; t++) bd[t] = 3.0e38f;
    float gate = 3.0e38f;
    float tq0 = 0.f, tq1 = 0.f, tq2 = 0.f, tq3 = 0.f;
    int cnt = 0;

#pragma unroll 2
    for (int j = 0; j < 512; j++) {
        int pi = (j << 2) | part;                  // pair index; candidates 2pi, 2pi+1
        u64 X = sX[pi], Y = sY[pi], Z = sZ[pi], S = sS[pi];
        u64 cr; MUL2(cr, qxp, X); FMA2(cr, qyp, Y); FMA2(cr, qzp, Z);
        u64 dd; ADD2(dd, q2p, S); FMA2(dd, m2p, cr);
        float d0, d1; UNPK2(d0, d1, dd);
        if (d0 <= gate) { tq3 = tq2; tq2 = tq1; tq1 = tq0; tq0 = d0; cnt++; }
        if (d1 <= gate) { tq3 = tq2; tq2 = tq1; tq1 = tq0; tq0 = d1; cnt++; }
        if (__ballot_sync(0xffffffffu, cnt >= 3)) {
            if (cnt >= 1) INSERT16(tq0);
            if (cnt >= 2) INSERT16(tq1);
            if (cnt >= 3) INSERT16(tq2);
            if (cnt >= 4) INSERT16(tq3);
            cnt = 0;
            float w = bd[0];
            w = fminf(w, __shfl_xor_sync(0xffffffffu, w, 1));
            w = fminf(w, __shfl_xor_sync(0xffffffffu, w, 2));
            gate = w;
        }
    }
    if (cnt >= 1) INSERT16(tq0);
    if (cnt >= 2) INSERT16(tq1);
    if (cnt >= 3) INSERT16(tq2);
    if (cnt >= 4) INSERT16(tq3);

#pragma unroll
    for (int r = 0; r < 16; r++) svals[ql*64 + part*16 + r] = bd[15-r];
    __syncthreads();

    // Phase 1.5: 4-list merge -> thr (one thread per query)
    if (part == 0) {
        const float* L = svals + ql*64;
        int p0 = 0, p1 = 0, p2 = 0, p3 = 0;
        float last = 0.f;
        for (int r = 0; r < 16; r++) {
            float v0 = L[p0], v1 = L[16+p1], v2 = L[32+p2], v3 = L[48+p3];
            float m;
            if (v0 <= v1 && v0 <= v2 && v0 <= v3) { m = v0; p0++; }
            else if (v1 <= v2 && v1 <= v3)        { m = v1; p1++; }
            else if (v2 <= v3)                    { m = v2; p2++; }
            else                                  { m = v3; p3++; }
            last = m;
        }
        sthr[ql] = last;
    }
    __syncthreads();     // after this, svals is dead -> sless/seq may overlay it

    // Phase 2: rescan with identical packed arithmetic; collect indices
    float thr = sthr[ql];
#pragma unroll 2
    for (int j = 0; j < 512; j++) {
        int pi = (j << 2) | part;
        u64 X = sX[pi], Y = sY[pi], Z = sZ[pi], S = sS[pi];
        u64 cr; MUL2(cr, qxp, X); FMA2(cr, qyp, Y); FMA2(cr, qzp, Z);
        u64 dd; ADD2(dd, q2p, S); FMA2(dd, m2p, cr);
        float d0, d1; UNPK2(d0, d1, dd);
        if (d0 <= thr) {
            int i = pi*2;
            if (d0 < thr) {
                int pos = atomicAdd(&scnt[ql*2 + 0], 1);
                sless[ql*16 + pos] = i;            // provably pos <= 14
            } else {
                int pos = atomicAdd(&scnt[ql*2 + 1], 1);
                if (pos < 32) seq[ql*32 + pos] = i;
            }
        }
        if (d1 <= thr) {
            int i = pi*2 + 1;
            if (d1 < thr) {
                int pos = atomicAdd(&scnt[ql*2 + 0], 1);
                sless[ql*16 + pos] = i;
            } else {
                int pos = atomicAdd(&scnt[ql*2 + 1], 1);
                if (pos < 32) seq[ql*32 + pos] = i;
            }
        }
    }
    __syncthreads();

    // Finalize: sort the <thr indices, append `need` smallest ==thr indices
    if (part == 0) {
        int nl = scnt[ql*2 + 0];
        int ne = scnt[ql*2 + 1]; if (ne > 32) ne = 32;
        int need = 16 - nl;
        int* Ls = sless + ql*16;
        for (int a = 1; a < nl; a++) {
            int v = Ls[a]; int bp = a;
            while (bp > 0 && Ls[bp-1] > v) { Ls[bp] = Ls[bp-1]; bp--; }
            Ls[bp] = v;
        }
        int* Es = seq + ql*32;
        int base = (b*NPT + n)*16;
        for (int r = 0; r < nl; r++) out[base + r] = Ls[r];
        for (int r = 0; r < need; r++) {
            int mi = 0x7fffffff, mp = 0;
            for (int a = 0; a < ne; a++) if (Es[a] < mi) { mi = Es[a]; mp = a; }
            Es[mp] = 0x7fffffff;
            out[base + nl + r] = mi;
        }
    }
}

// ---------------- group1 (k-loop fused away via Wmk1 = wm1@wk1) ----------------
#define GSZ1 2784
#define G1_SMEM ((10896 + 4*GSZ1)*4)
__global__ __launch_bounds__(256, 2) void group1_kernel(const float* __restrict__ wm2,
                                                        const float* __restrict__ bpos1,
                                                        int groups_total, int iters)
{
    extern __shared__ float sm[];
    float* s_wv1   = sm;                 // 8448  [o][132]
    float* s_Wmk1T = s_wv1 + 8448;       // 1024  [c][16] (negated)
    float* s_WmqT  = s_Wmk1T + 1024;     // 1024  [c][16]
    float* s_wp1T  = s_WmqT + 1024;      // 320   [r][64]
    float* s_wm2   = s_wp1T + 320;       // 16
    float* s_b1    = s_wm2  + 16;        // 64
    float* s_grp0  = s_b1   + 64;

    int tid = threadIdx.x;
    for (int i = tid; i < 8448; i += 256) s_wv1[i] = g_wv1R[i];
    for (int i = tid; i < 1024; i += 256) { s_Wmk1T[i] = g_Wmk1T[i]; s_WmqT[i] = g_WmqT[i]; }
    for (int i = tid; i < 320;  i += 256) s_wp1T[i] = g_wp1T[i];
    if (tid < 16) s_wm2[tid] = wm2[tid];
    if (tid < 64) s_b1[tid] = bpos1[tid];

    int g = tid >> 6, o = tid & 63;
    float* snb  = s_grp0 + g*GSZ1;      // [64][20]
    float* svpe = snb  + 64*NBST;       // [64][20]
    float* spts = svpe + 64*NBST;       // 64
    float* spos = spts + 64;            // [5][16]
    float* smq  = spos + 80;            // 16
    float* slog = smq  + 16;            // 16
    float* sfn2 = slog + 16;            // 16 (cross-warp partials)
    float* smqp = sfn2 + 16;            // 16
    int*   sidx = (int*)(smqp + 16);    // 16
    int gg = blockIdx.x * 4 + g;
    int sU = o & 15, qt = o >> 4;       // distributed fn2/mq assignment
    __syncthreads();                    // weights visible to all groups

    for (int it = 0; it < iters; it++) {
        int p = gg + it * groups_total;
        bool active = p < NPTS;
        int b = p >> 12;

        if (active) {
            if (o < 16) sidx[o] = g_idx1[(p<<4) + o];
            spts[o] = g_f1T[(p<<6) + o];
        }
        GBAR(g);
        if (active) {
#pragma unroll
            for (int s = 0; s < 16; s++) {
                int id = sidx[s];
                snb[o*NBST + s] = g_f2T[(((b<<12) + id)<<6) + o];
            }
        }
        GBAR(g);

        // vbase = wv1[o][0:64] . pts
        float vbase = 0.f;
        {
            const float4* wr4 = (const float4*)(s_wv1 + o*WV1S);
            const float4* pt4 = (const float4*)spts;
#pragma unroll 4
            for (int c4 = 0; c4 < 16; c4++) {
                float4 wv = wr4[c4]; float4 pv = pt4[c4];
                vbase += wv.x*pv.x; vbase += wv.y*pv.y;
                vbase += wv.z*pv.z; vbase += wv.w*pv.w;
            }
        }

        // distributed fn2 / mq: 4 threads per neighbor s, 16 channels each
        {
            float fn2p = 0.f, mqp = 0.f;
#pragma unroll
            for (int cc = 0; cc < 16; cc++) {
                int c = qt*16 + cc;
                float pv = spts[c];
                float t = pv - snb[c*NBST + sU];
                fn2p = __fmaf_rn(t, t, fn2p);
                mqp  = __fmaf_rn(s_WmqT[c*16 + sU], pv, mqp);
            }
            fn2p += __shfl_xor_sync(0xffffffffu, fn2p, 16);
            mqp  += __shfl_xor_sync(0xffffffffu, mqp, 16);
            if (o >= 32 && o < 48) { sfn2[sU] = fn2p; smqp[sU] = mqp; }
            GBAR(g);
            if (active && o < 16) {
                int s = o; int id = sidx[s];
                const float* q3 = g_x1T + p*3;
                const float* c3 = g_x2T + ((b<<12) + id)*3;
                float dx = q3[0]-c3[0], dy = q3[1]-c3[1], dz = q3[2]-c3[2];
                spos[0*16+s] = sqrtf(fn2p + sfn2[s]);
                spos[1*16+s] = sqrtf(dx*dx + dy*dy + dz*dz);
                spos[2*16+s] = dx; spos[3*16+s] = dy; spos[4*16+s] = dz;
                smq[s] = mqp + smqp[s];
            }
        }
        GBAR(g);

        // v[s] packed
        u64 va[8];
        {
            u64 vb2; PACK2(vb2, vbase, vbase);
#pragma unroll
            for (int k = 0; k < 8; k++) va[k] = vb2;
        }
#pragma unroll
        for (int jj = 0; jj < 3; jj++) {
            float wj = s_wv1[o*WV1S + 128 + jj];
            u64 ww; PACK2(ww, wj, wj);
            ACC16P(va, ww, spos + (2+jj)*16);
        }
        {
            const float4* wn4 = (const float4*)(s_wv1 + o*WV1S + 64);
#pragma unroll 4
            for (int c4 = 0; c4 < 16; c4++) {
                float4 wv = wn4[c4];
                u64 w0, w1, w2, w3;
                PACK2(w0, wv.x, wv.x); PACK2(w1, wv.y, wv.y);
                PACK2(w2, wv.z, wv.z); PACK2(w3, wv.w, wv.w);
                ACC16P(va, w0, snb + (c4*4+0)*NBST);
                ACC16P(va, w1, snb + (c4*4+1)*NBST);
                ACC16P(va, w2, snb + (c4*4+2)*NBST);
                ACC16P(va, w3, snb + (c4*4+3)*NBST);
            }
        }
        // pos_enc packed
        u64 pea[8];
        {
            float bb = s_b1[o];
            u64 bb2; PACK2(bb2, bb, bb);
#pragma unroll
            for (int k = 0; k < 8; k++) pea[k] = bb2;
        }
#pragma unroll
        for (int r = 0; r < 5; r++) {
            float wr = s_wp1T[r*64 + o];
            u64 ww; PACK2(ww, wr, wr);
            ACC16P(pea, ww, spos + r*16);
        }
        // svpe = v + pe
        {
            ulonglong2* dst = (ulonglong2*)(svpe + o*NBST);
#pragma unroll
            for (int k = 0; k < 4; k++) {
                u64 lo, hi;
                ADD2(lo, va[2*k],   pea[2*k]);
                ADD2(hi, va[2*k+1], pea[2*k+1]);
                ulonglong2 w2v; w2v.x = lo; w2v.y = hi;
                dst[k] = w2v;
            }
        }
        GBAR(g);

        // attn logits: h = relu(mq - Wmk1 @ (v+pe))  (fused; Wmk1 pre-negated)
        {
            int j = o & 15, sb = o >> 4;
            float mqj = smq[j];
            u64 hp0, hp1;
            PACK2(hp0, mqj, mqj); PACK2(hp1, mqj, mqj);
#pragma unroll 8
            for (int c = 0; c < 64; c++) {
                float w = s_Wmk1T[c*16 + j];     // = -(wm1@wk1)
                u64 ww; PACK2(ww, w, w);
                const ulonglong2* vp = (const ulonglong2*)(svpe + c*NBST + sb*4);
                ulonglong2 vv2 = vp[0];
                FMA2(hp0, ww, vv2.x);
                FMA2(hp1, ww, vv2.y);
            }
            float h0, h1, h2, h3;
            UNPK2(h0, h1, hp0); UNPK2(h2, h3, hp1);
            float wj = s_wm2[j];
            float hq[4] = {h0, h1, h2, h3};
#pragma unroll
            for (int ss = 0; ss < 4; ss++) {
                float part = wj * fmaxf(hq[ss], 0.f);
                part += __shfl_xor_sync(0xffffffffu, part, 1);
                part += __shfl_xor_sync(0xffffffffu, part, 2);
                part += __shfl_xor_sync(0xffffffffu, part, 4);
                part += __shfl_xor_sync(0xffffffffu, part, 8);
                if (j == 0) slog[sb*4 + ss] = part;
            }
        }
        GBAR(g);

        // softmax + weighted sum + leaky
        float v[16];
#pragma unroll
        for (int k = 0; k < 8; k++) UNPK2(v[2*k], v[2*k+1], va[k]);
        float mx = -3.0e38f;
#pragma unroll
        for (int s = 0; s < 16; s++) mx = fmaxf(mx, slog[s]);
        float sum = 0.f, outv = 0.f;
#pragma unroll
        for (int s = 0; s < 16; s++) {
            float e = __expf(slog[s] - mx);
            sum += e; outv += e * v[s];
        }
        outv /= sum;
        outv = (outv >= 0.f) ? outv : 0.1f*outv;
        if (active) g_p2nT[(p<<6) + o] = outv;
        GBAR(g);
    }
}

// ---------------- group2 (k-loop fused away via qw = q^T wk2) ----------------
#define GSZ2 2880
#define G2_SMEM ((13376 + 4*GSZ2)*4)
__global__ __launch_bounds__(256, 2) void group2_kernel(const float* __restrict__ bpos2,
                                                        float* __restrict__ outp,
                                                        int groups_total, int iters)
{
    extern __shared__ float sm[];
    float* s_wq2  = sm;                 // 4352 [o][68]
    float* s_wv2  = s_wq2 + 4352;       // 4352 [o][68]
    float* s_wk2C = s_wv2 + 4352;       // 4352 [c][68]
    float* s_wp2T = s_wk2C + 4352;      // 256
    float* s_b2   = s_wp2T + 256;       // 64
    float* s_grp0 = s_b2   + 64;        // 13376

    int tid = threadIdx.x;
    for (int i = tid; i < 4352; i += 256) {
        s_wq2[i] = g_wq2R[i]; s_wv2[i] = g_wv2R[i]; s_wk2C[i] = g_wk2C[i];
    }
    for (int i = tid; i < 256; i += 256) s_wp2T[i] = g_wp2T[i];
    if (tid < 64) s_b2[tid] = bpos2[tid];

    int g = tid >> 6, o = tid & 63;
    float* snb  = s_grp0 + g*GSZ2;      // [64][20] 1280
    float* stmp = snb  + 64*NBST;       // [64][20] 1280
    float* spts = stmp + 64*NBST;       // 64
    float* spos = spts + 64;            // [4][16]
    float* slog = spos + 64;            // 16
    float* sred = slog + 16;            // 16
    float* sq   = sred + 16;            // 64
    float* sqw  = sq   + 64;            // 64
    int*   sidx = (int*)(sqw + 64);     // 16
    int gg = blockIdx.x * 4 + g;
    int sU = o & 15, qt = o >> 4;
    __syncthreads();                    // weights visible to all groups

    for (int it = 0; it < iters; it++) {
        int p = gg + it * groups_total;
        bool active = p < NPTS;
        int b = p >> 12, n = p & (NPT-1);

        if (active) {
            if (o < 16) sidx[o] = g_idx2[(p<<4) + o];
            spts[o] = g_p2nT[(p<<6) + o];
        }
        GBAR(g);

        // neighbor gather + q + xyz in one phase
        if (active) {
#pragma unroll
            for (int s = 0; s < 16; s++) {
                int id = sidx[s];
                snb[o*NBST + s] = g_p2nT[(((b<<12) + id)<<6) + o];
            }
        }
        {
            float q = 0.f;
            const float4* wr4 = (const float4*)(s_wq2 + o*W64S);
            const float4* pt4 = (const float4*)spts;
#pragma unroll 4
            for (int c4 = 0; c4 < 16; c4++) {
                float4 wv = wr4[c4]; float4 pv = pt4[c4];
                q += wv.x*pv.x; q += wv.y*pv.y; q += wv.z*pv.z; q += wv.w*pv.w;
            }
            sq[o] = q * 0.125f;   // 64^-0.5
        }
        if (active && o < 16) {
            int s = o; int id = sidx[s];
            const float* q3 = g_x1T + p*3;
            const float* c3 = g_x1T + ((b<<12) + id)*3;
            float dx = q3[0]-c3[0], dy = q3[1]-c3[1], dz = q3[2]-c3[2];
            spos[0*16+s] = dx; spos[1*16+s] = dy; spos[2*16+s] = dz;
            spos[3*16+s] = sqrtf(dx*dx + dy*dy + dz*dz);
        }
        GBAR(g);

        // qw[c] = sum_o sq[o] * wk2[o][c]  (thread o computes c=o)
        {
            float qw = 0.f;
            const float4* wc4 = (const float4*)(s_wk2C + o*W64S);
            const float4* sq4 = (const float4*)sq;
#pragma unroll 4
            for (int c4 = 0; c4 < 16; c4++) {
                float4 wv = wc4[c4]; float4 qv = sq4[c4];
                qw += wv.x*qv.x; qw += wv.y*qv.y; qw += wv.z*qv.z; qw += wv.w*qv.w;
            }
            sqw[o] = qw;
        }
        // pos_enc packed + stmp = nb + pe
        {
            u64 pea[8];
            float bb = s_b2[o];
            u64 bb2; PACK2(bb2, bb, bb);
#pragma unroll
            for (int k = 0; k < 8; k++) pea[k] = bb2;
#pragma unroll
            for (int r = 0; r < 4; r++) {
                float wr = s_wp2T[r*64 + o];
                u64 ww; PACK2(ww, wr, wr);
                ACC16P(pea, ww, spos + r*16);
            }
            const ulonglong2* src = (const ulonglong2*)(snb + o*NBST);
            ulonglong2* dst = (ulonglong2*)(stmp + o*NBST);
#pragma unroll
            for (int k = 0; k < 4; k++) {
                ulonglong2 nbv = src[k];
                u64 lo, hi;
                ADD2(lo, nbv.x, pea[2*k]);
                ADD2(hi, nbv.y, pea[2*k+1]);
                ulonglong2 w2v; w2v.x = lo; w2v.y = hi;
                dst[k] = w2v;
            }
        }
        // v = wv2 @ nb  (packed)
        u64 vva[8];
#pragma unroll
        for (int k = 0; k < 8; k++) vva[k] = 0ull;
        {
            const float4* wv4 = (const float4*)(s_wv2 + o*W64S);
#pragma unroll 4
            for (int c4 = 0; c4 < 16; c4++) {
                float4 c = wv4[c4];
                u64 c0, c1, c2, c3;
                PACK2(c0, c.x, c.x); PACK2(c1, c.y, c.y);
                PACK2(c2, c.z, c.z); PACK2(c3, c.w, c.w);
                ACC16P(vva, c0, snb + (c4*4+0)*NBST);
                ACC16P(vva, c1, snb + (c4*4+1)*NBST);
                ACC16P(vva, c2, snb + (c4*4+2)*NBST);
                ACC16P(vva, c3, snb + (c4*4+3)*NBST);
            }
        }
        GBAR(g);

        // logits[s] = sum_c qw[c] * stmp[c][s]  (distributed: 4 threads per s)
        {
            float part = 0.f;
#pragma unroll
            for (int cc = 0; cc < 16; cc++) {
                int c = qt*16 + cc;
                part = __fmaf_rn(sqw[c], stmp[c*NBST + sU], part);
            }
            part += __shfl_xor_sync(0xffffffffu, part, 16);
            if (o >= 32 && o < 48) sred[sU] = part;
            GBAR(g);
            if (o < 16) slog[o] = part + sred[o];
        }
        GBAR(g);

        // softmax + weighted sum + leaky
        float vv[16];
#pragma unroll
        for (int k = 0; k < 8; k++) UNPK2(vv[2*k], vv[2*k+1], vva[k]);
        float mx = -3.0e38f;
#pragma unroll
        for (int s = 0; s < 16; s++) mx = fmaxf(mx, slog[s]);
        float sum = 0.f, outv = 0.f;
#pragma unroll
        for (int s = 0; s < 16; s++) {
            float e = __expf(slog[s] - mx);
            sum += e; outv += e * vv[s];
        }
        outv /= sum;
        outv = (outv >= 0.f) ? outv : 0.1f*outv;
        if (active) outp[(b*64 + o)*NPT + n] = outv;
        GBAR(g);
    }
}

// ---------------- launch ----------------
extern "C" void kernel_launch(void* const* d_in, const int* in_sizes, int n_in,
                              void* d_out, int out_size)
{
    const float* xyz1  = (const float*)d_in[0];
    const float* feat1 = (const float*)d_in[1];
    const float* xyz2  = (const float*)d_in[2];
    const float* feat2 = (const float*)d_in[3];
    const float* wq1   = (const float*)d_in[4];
    const float* wk1   = (const float*)d_in[5];
    const float* wv1   = (const float*)d_in[6];
    const float* wm1   = (const float*)d_in[7];
    const float* wm2   = (const float*)d_in[8];
    const float* wp1   = (const float*)d_in[9];
    const float* b1    = (const float*)d_in[10];
    const float* wq2   = (const float*)d_in[11];
    const float* wk2   = (const float*)d_in[12];
    const float* wv2   = (const float*)d_in[13];
    const float* wp2   = (const float*)d_in[14];
    const float* b2    = (const float*)d_in[15];
    float* out = (float*)d_out;

    cudaFuncSetAttribute(knn_both,      cudaFuncAttributeMaxDynamicSharedMemorySize, KNN_SMEM);
    cudaFuncSetAttribute(group1_kernel, cudaFuncAttributeMaxDynamicSharedMemorySize, G1_SMEM);
    cudaFuncSetAttribute(group2_kernel, cudaFuncAttributeMaxDynamicSharedMemorySize, G2_SMEM);

    const int GRID = 296;                 // 2 blocks/SM on 148 SMs
    const int GROUPS = GRID * 4;          // 1184 point-groups
    const int ITERS = (NPTS + GROUPS - 1) / GROUPS;   // 14

    transpose_feat<<<dim3(64, B4, 2), dim3(64, 8)>>>(feat1, feat2);                 // 0
    transpose_xyz_prep<<<dim3(64, 1, 2), 256>>>(xyz1, xyz2, wq1, wk1, wv1, wm1,
                                                wp1, wq2, wk2, wv2, wp2);           // 1
    knn_both<<<dim3(NPT/KQ, B4, 2), KTH, KNN_SMEM>>>(xyz1, xyz2);                   // 2
    group1_kernel<<<GRID, 256, G1_SMEM>>>(wm2, b1, GROUPS, ITERS);                  // 3 <- profiled
    group2_kernel<<<GRID, 256, G2_SMEM>>>(b2, out, GROUPS, ITERS);                  // 4
}